// round 3
// baseline (speedup 1.0000x reference)
#include <cuda_runtime.h>
#include <cuda_bf16.h>
#include <math.h>

#define HID   128
#define EF    4
#define NG    20
#define KIN   (2*HID + NG + EF)   // 280
#define TE    32                  // edges (or nodes) per block
#define PITCH 36                  // padded row stride (floats), 16B-aligned, limits bank conflicts
#define MAXN  20000
#define CUTOFF 10.0f

// -------------------- device scratch (no runtime alloc allowed) --------------------
__device__ float g_agg[MAXN * HID];   // message aggregation [N,128]
__device__ float g_dx [MAXN * 3];     // coordinate delta    [N,3]

// -------------------- shared layouts --------------------
struct __align__(16) EdgeSmem {
  alignas(16) float sA [KIN * PITCH];   // m_in^T  [280][32]
  alignas(16) float sM1[HID * PITCH];   // m1^T    [128][32]
  alignas(16) float sM2[HID * PITCH];   // m2^T    [128][32]
  float sRel[3][TE];
  float sRinv[TE];                      // 1/(r+1)
  float sR[TE];                         // r
  float sRedG[128];
  float sRedC[128];
  float sG[TE];
  float sC[TE];
  int   sDst[TE];
  int   sSrc[TE];
};

struct __align__(16) NodeSmem {
  alignas(16) float sA [2*HID * PITCH]; // [agg,h]^T [256][32]
  alignas(16) float sNM[HID * PITCH];   // nm^T      [128][32]
};

// -------------------- helpers --------------------
__device__ __forceinline__ float silu_f(float v) {
  return v / (1.f + __expf(-v));
}
__device__ __forceinline__ float sigmoid_f(float v) {
  return 1.f / (1.f + __expf(-v));
}
__device__ __forceinline__ float warp_sum(float v) {
  #pragma unroll
  for (int o = 16; o > 0; o >>= 1) v += __shfl_xor_sync(0xffffffffu, v, o);
  return v;
}

// 32-edge GEMV: thread j accumulates out[e][j] += sum_k A^T[k][e] * W[k][j]
// A^T staged in shared (broadcast float4 reads), W streamed from global (coalesced).
template<int K>
__device__ __forceinline__ void gemv32(const float* __restrict__ W,
                                       const float* __restrict__ sAT,
                                       int j, float acc[TE]) {
  #pragma unroll 4
  for (int k = 0; k < K; ++k) {
    float w = __ldg(W + k * HID + j);
    const float4* a4 = reinterpret_cast<const float4*>(sAT + k * PITCH);
    #pragma unroll
    for (int q = 0; q < TE/4; ++q) {
      float4 a = a4[q];
      acc[4*q+0] = fmaf(a.x, w, acc[4*q+0]);
      acc[4*q+1] = fmaf(a.y, w, acc[4*q+1]);
      acc[4*q+2] = fmaf(a.z, w, acc[4*q+2]);
      acc[4*q+3] = fmaf(a.w, w, acc[4*q+3]);
    }
  }
}

// -------------------- zero scratch --------------------
__global__ void zero_kernel() {
  int i = blockIdx.x * blockDim.x + threadIdx.x;
  if (i < MAXN * HID) g_agg[i] = 0.f;
  if (i < MAXN * 3)   g_dx[i]  = 0.f;
}

// -------------------- edge kernel --------------------
__global__ __launch_bounds__(128)
void edge_kernel(const float* __restrict__ h,   const float* __restrict__ x,
                 const float* __restrict__ ea,  const int*   __restrict__ ei,
                 const float* __restrict__ We1, const float* __restrict__ be1,
                 const float* __restrict__ We2, const float* __restrict__ be2,
                 const float* __restrict__ Wg,  const float* __restrict__ bg,
                 const float* __restrict__ Wx1, const float* __restrict__ bx1,
                 const float* __restrict__ Wx2, int E)
{
  extern __shared__ char smem_raw[];
  EdgeSmem& S = *reinterpret_cast<EdgeSmem*>(smem_raw);

  const int tid  = threadIdx.x;
  const int lane = tid & 31;
  const int wid  = tid >> 5;
  const int e0   = blockIdx.x * TE;

  // ---- edge indices (clamped for tail safety) ----
  if (tid < TE) {
    int eg = min(e0 + tid, E - 1);
    S.sSrc[tid] = ei[eg];
  } else if (tid < 2*TE) {
    int eg = min(e0 + tid - TE, E - 1);
    S.sDst[tid - TE] = ei[E + eg];
  }
  __syncthreads();

  // ---- geometry (warp 0) + h gathers (all threads) ----
  if (tid < TE) {
    int s = S.sSrc[tid], d = S.sDst[tid];
    float rx = x[d*3+0] - x[s*3+0];
    float ry = x[d*3+1] - x[s*3+1];
    float rz = x[d*3+2] - x[s*3+2];
    float d2 = rx*rx + ry*ry + rz*rz;
    float r  = sqrtf(d2 + 1e-8f);
    S.sRel[0][tid] = rx; S.sRel[1][tid] = ry; S.sRel[2][tid] = rz;
    S.sR[tid]    = r;
    S.sRinv[tid] = 1.f / (r + 1.f);
  }
  // rows 0..127 = h[dst], 128..255 = h[src]  (coalesced 512B global reads)
  #pragma unroll 4
  for (int e = 0; e < TE; ++e) {
    int d = S.sDst[e], s = S.sSrc[e];
    S.sA[tid * PITCH + e]         = __ldg(h + (size_t)d * HID + tid);
    S.sA[(HID + tid) * PITCH + e] = __ldg(h + (size_t)s * HID + tid);
  }
  __syncthreads();

  // ---- RBF rows 256..275 + edge_attr rows 276..279 ----
  {
    const float step  = CUTOFF / 19.f;
    const float coeff = -0.5f / (step * step);
    for (int idx = tid; idx < NG * TE; idx += 128) {
      int gi = idx >> 5, e = idx & 31;
      float diff = S.sR[e] - (float)gi * step;
      S.sA[(2*HID + gi) * PITCH + e] = __expf(coeff * diff * diff);
    }
    int fi = tid >> 5, e = tid & 31;              // 4 feats x 32 edges = 128
    int eg = min(e0 + e, E - 1);
    S.sA[(2*HID + NG + fi) * PITCH + e] = ea[(size_t)eg * EF + fi];
  }
  __syncthreads();

  // ---- stage 1: m1 = silu(m_in @ W_e1 + b_e1) ----
  float acc[TE];
  #pragma unroll
  for (int e = 0; e < TE; ++e) acc[e] = 0.f;
  gemv32<KIN>(We1, S.sA, tid, acc);
  {
    float b1 = __ldg(be1 + tid);
    #pragma unroll
    for (int e = 0; e < TE; ++e) {
      float v = silu_f(acc[e] + b1);
      acc[e] = v;
      S.sM1[tid * PITCH + e] = v;
    }
  }
  __syncthreads();

  // ---- stage 2: m2 = silu(m1 @ W_e2 + b_e2) ----
  #pragma unroll
  for (int e = 0; e < TE; ++e) acc[e] = 0.f;
  gemv32<HID>(We2, S.sM1, tid, acc);
  {
    float b2 = __ldg(be2 + tid);
    #pragma unroll
    for (int e = 0; e < TE; ++e) {
      float v = silu_f(acc[e] + b2);
      acc[e] = v;                       // acc now holds m2[e][tid]
      S.sM2[tid * PITCH + e] = v;
    }
  }
  __syncthreads();

  // ---- stage 3: t = silu(m2 @ W_x1 + b_x1); contribution t*W_x2[j] ----
  float acc3[TE];
  #pragma unroll
  for (int e = 0; e < TE; ++e) acc3[e] = 0.f;
  gemv32<HID>(Wx1, S.sM2, tid, acc3);
  {
    float bx = __ldg(bx1 + tid);
    float w2 = __ldg(Wx2 + tid);
    #pragma unroll
    for (int e = 0; e < TE; ++e)
      acc3[e] = silu_f(acc3[e] + bx) * w2;
  }

  // ---- reductions over j: gate g[e] and coef[e] ----
  {
    float wg = __ldg(Wg + tid);
    #pragma unroll
    for (int e = 0; e < TE; ++e) {
      float vg = warp_sum(acc[e] * wg);
      float vc = warp_sum(acc3[e]);
      if (lane == 0) { S.sRedG[wid*32 + e] = vg; S.sRedC[wid*32 + e] = vc; }
    }
  }
  __syncthreads();
  if (tid < TE) {
    float sg = S.sRedG[tid] + S.sRedG[32+tid] + S.sRedG[64+tid] + S.sRedG[96+tid] + bg[0];
    S.sG[tid] = sigmoid_f(sg);
    float sc = S.sRedC[tid] + S.sRedC[32+tid] + S.sRedC[64+tid] + S.sRedC[96+tid];
    S.sC[tid] = tanhf(sc);
  }
  __syncthreads();

  // ---- scatter: msg = m2 * g into agg[dst]; vec into dx[dst] ----
  #pragma unroll 4
  for (int e = 0; e < TE; ++e) {
    if (e0 + e < E) {
      atomicAdd(&g_agg[(size_t)S.sDst[e] * HID + tid], acc[e] * S.sG[e]);
    }
  }
  if (tid < TE && (e0 + tid < E)) {
    int e = tid;
    int d = S.sDst[e];
    float c = S.sC[e] * S.sRinv[e];
    atomicAdd(&g_dx[d*3+0], S.sRel[0][e] * c);
    atomicAdd(&g_dx[d*3+1], S.sRel[1][e] * c);
    atomicAdd(&g_dx[d*3+2], S.sRel[2][e] * c);
  }
}

// -------------------- node kernel --------------------
__global__ __launch_bounds__(128)
void node_kernel(const float* __restrict__ h,   const float* __restrict__ x,
                 const float* __restrict__ Wn1, const float* __restrict__ bn1,
                 const float* __restrict__ Wn2, const float* __restrict__ bn2,
                 const int*   __restrict__ mask,
                 float* __restrict__ outH, float* __restrict__ outX, int N)
{
  extern __shared__ char smem_raw[];
  NodeSmem& S = *reinterpret_cast<NodeSmem*>(smem_raw);

  const int tid = threadIdx.x;
  const int n0  = blockIdx.x * TE;

  // stage [agg | h] transposed  (rows 0..127 agg, 128..255 h)
  #pragma unroll 4
  for (int e = 0; e < TE; ++e) {
    int n = min(n0 + e, N - 1);
    S.sA[tid * PITCH + e]         = g_agg[(size_t)n * HID + tid];
    S.sA[(HID + tid) * PITCH + e] = __ldg(h + (size_t)n * HID + tid);
  }
  __syncthreads();

  // nm = silu([agg,h] @ W_n1 + b_n1)
  float acc[TE];
  #pragma unroll
  for (int e = 0; e < TE; ++e) acc[e] = 0.f;
  gemv32<2*HID>(Wn1, S.sA, tid, acc);
  {
    float b1 = __ldg(bn1 + tid);
    #pragma unroll
    for (int e = 0; e < TE; ++e)
      S.sNM[tid * PITCH + e] = silu_f(acc[e] + b1);
  }
  __syncthreads();

  // h_out = h + nm @ W_n2 + b_n2
  #pragma unroll
  for (int e = 0; e < TE; ++e) acc[e] = 0.f;
  gemv32<HID>(Wn2, S.sNM, tid, acc);
  {
    float b2 = __ldg(bn2 + tid);
    #pragma unroll
    for (int e = 0; e < TE; ++e) {
      int n = n0 + e;
      if (n < N) {
        float hv = S.sA[(HID + tid) * PITCH + e];   // h[n][tid] already staged
        outH[(size_t)n * HID + tid] = hv + acc[e] + b2;
      }
    }
  }

  // x_out = x + dx * mask
  if (tid < 3 * TE) {
    int e = tid / 3, comp = tid - e * 3;
    int n = n0 + e;
    if (n < N) {
      float m = (float)mask[n];
      outX[n*3 + comp] = x[n*3 + comp] + g_dx[n*3 + comp] * m;
    }
  }
}

// -------------------- launch --------------------
extern "C" void kernel_launch(void* const* d_in, const int* in_sizes, int n_in,
                              void* d_out, int out_size) {
  const float *h, *x, *ea, *We1, *be1, *We2, *be2, *Wg, *bg;
  const float *Wn1, *bn1, *Wn2, *bn2, *Wx1, *bx1, *Wx2;
  const int *ei, *mask;

  const int E = in_sizes[2] / EF;           // edge_attr is index 2 in both orders
  const int N = in_sizes[0] / HID;          // h is index 0 in both orders

  // Disambiguate input ordering at runtime:
  //  setup_inputs dict order: idx3 = edge_index (2*E elements)
  //  reference signature order: idx3 = W_e1 (280*128 = 35840 elements)
  const bool setup_order = (in_sizes[3] == 2 * E);

  if (setup_order) {
    h    = (const float*)d_in[0];  x    = (const float*)d_in[1];
    ea   = (const float*)d_in[2];  ei   = (const int*)  d_in[3];
    mask = (const int*)  d_in[4];
    We1  = (const float*)d_in[5];  be1  = (const float*)d_in[6];
    We2  = (const float*)d_in[7];  be2  = (const float*)d_in[8];
    Wg   = (const float*)d_in[9];  bg   = (const float*)d_in[10];
    Wn1  = (const float*)d_in[11]; bn1  = (const float*)d_in[12];
    Wn2  = (const float*)d_in[13]; bn2  = (const float*)d_in[14];
    Wx1  = (const float*)d_in[15]; bx1  = (const float*)d_in[16];
    Wx2  = (const float*)d_in[17];
  } else {
    h    = (const float*)d_in[0];  x    = (const float*)d_in[1];
    ea   = (const float*)d_in[2];
    We1  = (const float*)d_in[3];  be1  = (const float*)d_in[4];
    We2  = (const float*)d_in[5];  be2  = (const float*)d_in[6];
    Wg   = (const float*)d_in[7];  bg   = (const float*)d_in[8];
    Wn1  = (const float*)d_in[9];  bn1  = (const float*)d_in[10];
    Wn2  = (const float*)d_in[11]; bn2  = (const float*)d_in[12];
    Wx1  = (const float*)d_in[13]; bx1  = (const float*)d_in[14];
    Wx2  = (const float*)d_in[15];
    ei   = (const int*)  d_in[16]; mask = (const int*)  d_in[17];
  }

  float* outH = (float*)d_out;
  float* outX = outH + (size_t)N * HID;

  cudaFuncSetAttribute(edge_kernel, cudaFuncAttributeMaxDynamicSharedMemorySize,
                       (int)sizeof(EdgeSmem));
  cudaFuncSetAttribute(node_kernel, cudaFuncAttributeMaxDynamicSharedMemorySize,
                       (int)sizeof(NodeSmem));

  zero_kernel<<<(MAXN * HID + 255) / 256, 256>>>();

  int eblocks = (E + TE - 1) / TE;
  edge_kernel<<<eblocks, 128, sizeof(EdgeSmem)>>>(
      h, x, ea, ei, We1, be1, We2, be2, Wg, bg, Wx1, bx1, Wx2, E);

  int nblocks = (N + TE - 1) / TE;
  node_kernel<<<nblocks, 128, sizeof(NodeSmem)>>>(
      h, x, Wn1, bn1, Wn2, bn2, mask, outH, outX, N);
}

// round 5
// speedup vs baseline: 2.0153x; 2.0153x over previous
#include <cuda_runtime.h>
#include <cuda_bf16.h>
#include <math.h>

#define HID   128
#define EF    4
#define NG    20
#define KIN   (2*HID + NG + EF)   // 280
#define TE    32                  // edges (or nodes) per block
#define PITCH 36                  // padded row stride (floats); 144B, 16B aligned
#define MAXN  20000
#define CUTOFF 10.0f

typedef unsigned long long ull;

// -------------------- device scratch (no runtime alloc allowed) --------------------
__device__ float g_agg[MAXN * HID];   // message aggregation [N,128]
__device__ float g_dx [MAXN * 3];     // coordinate delta    [N,3]

// -------------------- packed f32x2 helpers (Blackwell FFMA2 path) --------------------
__device__ __forceinline__ ull fma2(ull a, ull b, ull c) {
  ull d;
  asm("fma.rn.f32x2 %0, %1, %2, %3;" : "=l"(d) : "l"(a), "l"(b), "l"(c));
  return d;
}
__device__ __forceinline__ ull pack_dup(float v) {
  ull d; unsigned u = __float_as_uint(v);
  asm("mov.b64 %0, {%1, %1};" : "=l"(d) : "r"(u));
  return d;
}
__device__ __forceinline__ ull pack2(float a, float b) {
  ull d;
  asm("mov.b64 %0, {%1, %2};" : "=l"(d) : "r"(__float_as_uint(a)), "r"(__float_as_uint(b)));
  return d;
}
__device__ __forceinline__ float2 unpack2(ull v) {
  unsigned lo, hi;
  asm("mov.b64 {%0, %1}, %2;" : "=r"(lo), "=r"(hi) : "l"(v));
  return make_float2(__uint_as_float(lo), __uint_as_float(hi));
}

__device__ __forceinline__ float silu_f(float v)    { return v / (1.f + __expf(-v)); }
__device__ __forceinline__ float sigmoid_f(float v) { return 1.f / (1.f + __expf(-v)); }
__device__ __forceinline__ float warp_sum(float v) {
  #pragma unroll
  for (int o = 16; o > 0; o >>= 1) v += __shfl_xor_sync(0xffffffffu, v, o);
  return v;
}

// Packed 32-edge GEMV: thread j accumulates out[e][j] += A^T[k][e] * W[k][j]
// A^T rows broadcast from shared as ulonglong2 (LDS.128), weight streamed from
// global (coalesced, L1-resident) and duplicated into an f32x2 pair once per k.
template<int K>
__device__ __forceinline__ void gemv32p(const float* __restrict__ W,
                                        const float* __restrict__ sAT,
                                        int j, ull acc[16]) {
  #pragma unroll 4
  for (int k = 0; k < K; ++k) {
    ull w2 = pack_dup(__ldg(W + k * HID + j));
    const ulonglong2* a2 = reinterpret_cast<const ulonglong2*>(sAT + k * PITCH);
    #pragma unroll
    for (int q = 0; q < 8; ++q) {
      ulonglong2 v = a2[q];
      acc[2*q]   = fma2(v.x, w2, acc[2*q]);
      acc[2*q+1] = fma2(v.y, w2, acc[2*q+1]);
    }
  }
}

// -------------------- shared layouts --------------------
// Edge kernel aliases intermediate tiles into the big m_in staging buffer:
//   sA rows [0..279]   : m_in^T during stage 1
//   sA rows [0..127]   : m1^T  (overwritten after stage 1, guarded by syncs)
//   sA rows [128..255] : m2^T  (overwritten after stage 2)
struct __align__(16) EdgeSmem {
  alignas(16) float sA[KIN * PITCH];    // 280 x 36 floats = 40320 B
  float sRel[3][TE];
  float sRinv[TE];
  float sR[TE];
  float sRedG[128];
  float sRedC[128];
  float sG[TE];
  float sC[TE];
  int   sDst[TE];
  int   sSrc[TE];
};

// Node kernel: sA rows [0..127]=agg^T, [128..255]=h^T; nm^T aliases rows [0..127].
struct __align__(16) NodeSmem {
  alignas(16) float sA[2*HID * PITCH];
};

// -------------------- zero scratch --------------------
__global__ void zero_kernel() {
  int i = blockIdx.x * blockDim.x + threadIdx.x;
  if (i < MAXN * HID) g_agg[i] = 0.f;
  if (i < MAXN * 3)   g_dx[i]  = 0.f;
}

// -------------------- edge kernel --------------------
__global__ __launch_bounds__(128, 4)
void edge_kernel(const float* __restrict__ h,   const float* __restrict__ x,
                 const float* __restrict__ ea,  const int*   __restrict__ ei,
                 const float* __restrict__ We1, const float* __restrict__ be1,
                 const float* __restrict__ We2, const float* __restrict__ be2,
                 const float* __restrict__ Wg,  const float* __restrict__ bg,
                 const float* __restrict__ Wx1, const float* __restrict__ bx1,
                 const float* __restrict__ Wx2, int E)
{
  extern __shared__ char smem_raw[];
  EdgeSmem& S = *reinterpret_cast<EdgeSmem*>(smem_raw);
  float* sM1 = S.sA;                    // rows 0..127  (alias)
  float* sM2 = S.sA + HID * PITCH;      // rows 128..255 (alias)

  const int tid  = threadIdx.x;
  const int lane = tid & 31;
  const int wid  = tid >> 5;
  const int e0   = blockIdx.x * TE;

  // ---- edge indices ----
  if (tid < TE) {
    int eg = min(e0 + tid, E - 1);
    S.sSrc[tid] = ei[eg];
  } else if (tid < 2*TE) {
    int eg = min(e0 + tid - TE, E - 1);
    S.sDst[tid - TE] = ei[E + eg];
  }
  __syncthreads();

  // ---- geometry + h gathers ----
  if (tid < TE) {
    int s = S.sSrc[tid], d = S.sDst[tid];
    float rx = x[d*3+0] - x[s*3+0];
    float ry = x[d*3+1] - x[s*3+1];
    float rz = x[d*3+2] - x[s*3+2];
    float r  = sqrtf(rx*rx + ry*ry + rz*rz + 1e-8f);
    S.sRel[0][tid] = rx; S.sRel[1][tid] = ry; S.sRel[2][tid] = rz;
    S.sR[tid]    = r;
    S.sRinv[tid] = 1.f / (r + 1.f);
  }
  // rows 0..127 = h[dst]^T, 128..255 = h[src]^T  (coalesced 512B per warp reads)
  #pragma unroll 4
  for (int e = 0; e < TE; ++e) {
    int d = S.sDst[e], s = S.sSrc[e];
    S.sA[tid * PITCH + e]         = __ldg(h + (size_t)d * HID + tid);
    S.sA[(HID + tid) * PITCH + e] = __ldg(h + (size_t)s * HID + tid);
  }
  __syncthreads();

  // ---- RBF rows 256..275 + edge_attr rows 276..279 ----
  {
    const float step  = CUTOFF / 19.f;
    const float coeff = -0.5f / (step * step);
    for (int idx = tid; idx < NG * TE; idx += 128) {
      int gi = idx >> 5, e = idx & 31;
      float diff = S.sR[e] - (float)gi * step;
      S.sA[(2*HID + gi) * PITCH + e] = __expf(coeff * diff * diff);
    }
    int fi = tid >> 5, e = tid & 31;
    int eg = min(e0 + e, E - 1);
    S.sA[(2*HID + NG + fi) * PITCH + e] = ea[(size_t)eg * EF + fi];
  }
  __syncthreads();

  // ---- stage 1: m1 = silu(m_in @ W_e1 + b_e1) ----
  ull acc[16];
  #pragma unroll
  for (int q = 0; q < 16; ++q) acc[q] = 0ull;
  gemv32p<KIN>(We1, S.sA, tid, acc);
  {
    float b1 = __ldg(be1 + tid);
    #pragma unroll
    for (int q = 0; q < 16; ++q) {
      float2 v = unpack2(acc[q]);
      acc[q] = pack2(silu_f(v.x + b1), silu_f(v.y + b1));
    }
  }
  __syncthreads();                       // all warps done reading sA before alias write
  #pragma unroll
  for (int q = 0; q < 16; ++q) {
    float2 v = unpack2(acc[q]);
    sM1[tid * PITCH + 2*q]     = v.x;
    sM1[tid * PITCH + 2*q + 1] = v.y;
  }
  __syncthreads();

  // ---- stage 2: m2 = silu(m1 @ W_e2 + b_e2) ----
  #pragma unroll
  for (int q = 0; q < 16; ++q) acc[q] = 0ull;
  gemv32p<HID>(We2, sM1, tid, acc);
  {
    float b2 = __ldg(be2 + tid);
    #pragma unroll
    for (int q = 0; q < 16; ++q) {
      float2 v = unpack2(acc[q]);
      float r0 = silu_f(v.x + b2), r1 = silu_f(v.y + b2);
      acc[q] = pack2(r0, r1);            // acc now holds m2 (kept for gate+scatter)
      sM2[tid * PITCH + 2*q]     = r0;   // writes rows 128..255 — disjoint from reads
      sM2[tid * PITCH + 2*q + 1] = r1;
    }
  }
  __syncthreads();

  // ---- stage 3: t = silu(m2 @ W_x1 + b_x1) * W_x2[j] ----
  ull acc3[16];
  #pragma unroll
  for (int q = 0; q < 16; ++q) acc3[q] = 0ull;
  gemv32p<HID>(Wx1, sM2, tid, acc3);
  {
    float bx = __ldg(bx1 + tid);
    float w2 = __ldg(Wx2 + tid);
    #pragma unroll
    for (int q = 0; q < 16; ++q) {
      float2 v = unpack2(acc3[q]);
      acc3[q] = pack2(silu_f(v.x + bx) * w2, silu_f(v.y + bx) * w2);
    }
  }

  // ---- reductions over j: gate g[e] and coef[e] ----
  {
    float wg = __ldg(Wg + tid);
    #pragma unroll
    for (int q = 0; q < 16; ++q) {
      float2 m = unpack2(acc[q]);
      float2 c = unpack2(acc3[q]);
      float g0 = warp_sum(m.x * wg);
      float g1 = warp_sum(m.y * wg);
      float c0 = warp_sum(c.x);
      float c1 = warp_sum(c.y);
      if (lane == 0) {
        S.sRedG[wid*32 + 2*q]   = g0;  S.sRedG[wid*32 + 2*q+1] = g1;
        S.sRedC[wid*32 + 2*q]   = c0;  S.sRedC[wid*32 + 2*q+1] = c1;
      }
    }
  }
  __syncthreads();
  if (tid < TE) {
    float sg = S.sRedG[tid] + S.sRedG[32+tid] + S.sRedG[64+tid] + S.sRedG[96+tid] + bg[0];
    S.sG[tid] = sigmoid_f(sg);
    float sc = S.sRedC[tid] + S.sRedC[32+tid] + S.sRedC[64+tid] + S.sRedC[96+tid];
    S.sC[tid] = tanhf(sc);
  }
  __syncthreads();

  // ---- scatter: msg = m2 * g into agg[dst]; vec into dx[dst] ----
  #pragma unroll 4
  for (int q = 0; q < 16; ++q) {
    float2 m = unpack2(acc[q]);
    int eA = 2*q, eB = 2*q + 1;
    if (e0 + eA < E)
      atomicAdd(&g_agg[(size_t)S.sDst[eA] * HID + tid], m.x * S.sG[eA]);
    if (e0 + eB < E)
      atomicAdd(&g_agg[(size_t)S.sDst[eB] * HID + tid], m.y * S.sG[eB]);
  }
  if (tid < TE && (e0 + tid < E)) {
    int e = tid;
    int d = S.sDst[e];
    float c = S.sC[e] * S.sRinv[e];
    atomicAdd(&g_dx[d*3+0], S.sRel[0][e] * c);
    atomicAdd(&g_dx[d*3+1], S.sRel[1][e] * c);
    atomicAdd(&g_dx[d*3+2], S.sRel[2][e] * c);
  }
}

// -------------------- node kernel --------------------
__global__ __launch_bounds__(128, 4)
void node_kernel(const float* __restrict__ h,
                 const float* __restrict__ Wn1, const float* __restrict__ bn1,
                 const float* __restrict__ Wn2, const float* __restrict__ bn2,
                 float* __restrict__ outH, int N)
{
  extern __shared__ char smem_raw[];
  NodeSmem& S = *reinterpret_cast<NodeSmem*>(smem_raw);
  float* sNM = S.sA;                    // rows 0..127 alias (agg no longer needed)

  const int tid = threadIdx.x;
  const int n0  = blockIdx.x * TE;

  #pragma unroll 4
  for (int e = 0; e < TE; ++e) {
    int n = min(n0 + e, N - 1);
    S.sA[tid * PITCH + e]         = g_agg[(size_t)n * HID + tid];
    S.sA[(HID + tid) * PITCH + e] = __ldg(h + (size_t)n * HID + tid);
  }
  __syncthreads();

  // nm = silu([agg,h] @ W_n1 + b_n1)
  ull acc[16];
  #pragma unroll
  for (int q = 0; q < 16; ++q) acc[q] = 0ull;
  gemv32p<2*HID>(Wn1, S.sA, tid, acc);
  {
    float b1 = __ldg(bn1 + tid);
    #pragma unroll
    for (int q = 0; q < 16; ++q) {
      float2 v = unpack2(acc[q]);
      acc[q] = pack2(silu_f(v.x + b1), silu_f(v.y + b1));
    }
  }
  __syncthreads();
  #pragma unroll
  for (int q = 0; q < 16; ++q) {
    float2 v = unpack2(acc[q]);
    sNM[tid * PITCH + 2*q]     = v.x;
    sNM[tid * PITCH + 2*q + 1] = v.y;
  }
  __syncthreads();

  // h_out = h + nm @ W_n2 + b_n2
  #pragma unroll
  for (int q = 0; q < 16; ++q) acc[q] = 0ull;
  gemv32p<HID>(Wn2, sNM, tid, acc);
  {
    float b2 = __ldg(bn2 + tid);
    #pragma unroll
    for (int q = 0; q < 16; ++q) {
      float2 v = unpack2(acc[q]);
      int eA = 2*q, eB = 2*q + 1;
      if (n0 + eA < N) {
        float hv = S.sA[(HID + tid) * PITCH + eA];
        outH[(size_t)(n0 + eA) * HID + tid] = hv + v.x + b2;
      }
      if (n0 + eB < N) {
        float hv = S.sA[(HID + tid) * PITCH + eB];
        outH[(size_t)(n0 + eB) * HID + tid] = hv + v.y + b2;
      }
    }
  }
}

// -------------------- x update (separate tiny launch; also shifts ncu -s 5 onto edge_kernel) ----
__global__ void xout_kernel(const float* __restrict__ x, const int* __restrict__ mask,
                            float* __restrict__ outX, int N)
{
  int i = blockIdx.x * blockDim.x + threadIdx.x;
  if (i < N * 3) {
    int n = i / 3;
    outX[i] = x[i] + g_dx[i] * (float)mask[n];
  }
}

// -------------------- launch --------------------
extern "C" void kernel_launch(void* const* d_in, const int* in_sizes, int n_in,
                              void* d_out, int out_size) {
  const float *h, *x, *ea, *We1, *be1, *We2, *be2, *Wg, *bg;
  const float *Wn1, *bn1, *Wn2, *bn2, *Wx1, *bx1, *Wx2;
  const int *ei, *mask;

  const int E = in_sizes[2] / EF;
  const int N = in_sizes[0] / HID;
  const bool setup_order = (in_sizes[3] == 2 * E);

  if (setup_order) {
    h    = (const float*)d_in[0];  x    = (const float*)d_in[1];
    ea   = (const float*)d_in[2];  ei   = (const int*)  d_in[3];
    mask = (const int*)  d_in[4];
    We1  = (const float*)d_in[5];  be1  = (const float*)d_in[6];
    We2  = (const float*)d_in[7];  be2  = (const float*)d_in[8];
    Wg   = (const float*)d_in[9];  bg   = (const float*)d_in[10];
    Wn1  = (const float*)d_in[11]; bn1  = (const float*)d_in[12];
    Wn2  = (const float*)d_in[13]; bn2  = (const float*)d_in[14];
    Wx1  = (const float*)d_in[15]; bx1  = (const float*)d_in[16];
    Wx2  = (const float*)d_in[17];
  } else {
    h    = (const float*)d_in[0];  x    = (const float*)d_in[1];
    ea   = (const float*)d_in[2];
    We1  = (const float*)d_in[3];  be1  = (const float*)d_in[4];
    We2  = (const float*)d_in[5];  be2  = (const float*)d_in[6];
    Wg   = (const float*)d_in[7];  bg   = (const float*)d_in[8];
    Wn1  = (const float*)d_in[9];  bn1  = (const float*)d_in[10];
    Wn2  = (const float*)d_in[11]; bn2  = (const float*)d_in[12];
    Wx1  = (const float*)d_in[13]; bx1  = (const float*)d_in[14];
    Wx2  = (const float*)d_in[15];
    ei   = (const int*)  d_in[16]; mask = (const int*)  d_in[17];
  }

  float* outH = (float*)d_out;
  float* outX = outH + (size_t)N * HID;

  cudaFuncSetAttribute(edge_kernel, cudaFuncAttributeMaxDynamicSharedMemorySize,
                       (int)sizeof(EdgeSmem));
  cudaFuncSetAttribute(node_kernel, cudaFuncAttributeMaxDynamicSharedMemorySize,
                       (int)sizeof(NodeSmem));

  zero_kernel<<<(MAXN * HID + 255) / 256, 256>>>();

  int eblocks = (E + TE - 1) / TE;
  edge_kernel<<<eblocks, 128, sizeof(EdgeSmem)>>>(
      h, x, ea, ei, We1, be1, We2, be2, Wg, bg, Wx1, bx1, Wx2, E);

  int nblocks = (N + TE - 1) / TE;
  node_kernel<<<nblocks, 128, sizeof(NodeSmem)>>>(
      h, Wn1, bn1, Wn2, bn2, outH, N);

  xout_kernel<<<(N * 3 + 255) / 256, 256>>>(x, mask, outX, N);
}

// round 10
// speedup vs baseline: 3.2353x; 1.6053x over previous
#include <cuda_runtime.h>
#include <cuda_bf16.h>
#include <math.h>

#define HID   128
#define EF    4
#define NG    20
#define KREST (NG + EF)           // 24: rbf+ea rows of W_e1
#define TE    32                  // edges (or nodes) per block
#define PITCH 36                  // padded row stride (floats); 144B, 16B aligned
#define MAXN  20000
#define CUTOFF 10.0f

typedef unsigned long long ull;

// -------------------- device scratch (no runtime alloc) --------------------
__device__ float g_agg[MAXN * HID];     // message aggregation [N,128]
__device__ float g_dx [MAXN * 3];       // coordinate delta    [N,3]
__device__ float g_P  [MAXN * 256];     // [P_dst | P_src] per node (precomputed h@We1 halves)

// -------------------- packed f32x2 helpers (Blackwell FFMA2 path) --------------------
__device__ __forceinline__ ull fma2(ull a, ull b, ull c) {
  ull d;
  asm("fma.rn.f32x2 %0, %1, %2, %3;" : "=l"(d) : "l"(a), "l"(b), "l"(c));
  return d;
}
__device__ __forceinline__ ull pack_dup(float v) {
  ull d; unsigned u = __float_as_uint(v);
  asm("mov.b64 %0, {%1, %1};" : "=l"(d) : "r"(u));
  return d;
}
__device__ __forceinline__ ull pack2f(float a, float b) {
  ull d;
  asm("mov.b64 %0, {%1, %2};" : "=l"(d) : "r"(__float_as_uint(a)), "r"(__float_as_uint(b)));
  return d;
}
__device__ __forceinline__ float2 unpack2(ull v) {
  unsigned lo, hi;
  asm("mov.b64 {%0, %1}, %2;" : "=r"(lo), "=r"(hi) : "l"(v));
  return make_float2(__uint_as_float(lo), __uint_as_float(hi));
}

__device__ __forceinline__ float silu_f(float v)    { return v / (1.f + __expf(-v)); }
__device__ __forceinline__ float sigmoid_f(float v) { return 1.f / (1.f + __expf(-v)); }
__device__ __forceinline__ float warp_sum(float v) {
  #pragma unroll
  for (int o = 16; o > 0; o >>= 1) v += __shfl_xor_sync(0xffffffffu, v, o);
  return v;
}

// Packed 32-col GEMV: thread j accumulates out[e][j] += A^T[k][e] * W[k][j]
template<int K>
__device__ __forceinline__ void gemv32p(const float* __restrict__ W,
                                        const float* __restrict__ sAT,
                                        int j, ull acc[16]) {
  #pragma unroll 4
  for (int k = 0; k < K; ++k) {
    ull w2 = pack_dup(__ldg(W + k * HID + j));
    const ulonglong2* a2 = reinterpret_cast<const ulonglong2*>(sAT + k * PITCH);
    #pragma unroll
    for (int q = 0; q < 8; ++q) {
      ulonglong2 v = a2[q];
      acc[2*q]   = fma2(v.x, w2, acc[2*q]);
      acc[2*q+1] = fma2(v.y, w2, acc[2*q+1]);
    }
  }
}

// -------------------- shared layouts --------------------
struct __align__(16) EdgeSmem {
  alignas(16) float sRest[KREST * PITCH];   // [rbf|ea]^T [24][32]
  alignas(16) float sM1 [HID * PITCH];      // m1^T [128][32]
  alignas(16) float sM2 [HID * PITCH];      // m2^T [128][32]
  float sRel[3][TE];
  float sRinv[TE];
  float sR[TE];
  float sRedG[128];
  float sRedC[128];
  float sG[TE];
  float sC[TE];
  int   sDst[TE];
  int   sSrc[TE];
};

struct __align__(16) NodeSmem {
  alignas(16) float sA[2*HID * PITCH];      // [agg|h]^T; nm^T aliases rows 0..127
};

struct __align__(16) PrepSmem {
  alignas(16) float sH[HID * PITCH];        // h^T [128][32]
};

// -------------------- zero scratch --------------------
__global__ void zero_kernel() {
  int i = blockIdx.x * blockDim.x + threadIdx.x;
  if (i < MAXN * HID) g_agg[i] = 0.f;
  if (i < MAXN * 3)   g_dx[i]  = 0.f;
}

// -------------------- no-op (launch-slot alignment for ncu: edge lands on #4) ----
__global__ void noop_kernel() {}

// -------------------- precompute P = [h@We1_top | h@We1_mid] --------------------
__global__ __launch_bounds__(256, 3)
void prep_kernel(const float* __restrict__ h, const float* __restrict__ We1, int N)
{
  __shared__ PrepSmem S;
  const int tid = threadIdx.x;
  const int n0  = blockIdx.x * TE;

  // stage h^T for 32 nodes: thread pattern gives coalesced 512B reads
  for (int idx = tid; idx < HID * TE; idx += 256) {
    int row = idx & 127, e = idx >> 7;          // e in 0..1 per pass, 16 passes
    int n = min(n0 + e, N - 1);
    S.sH[row * PITCH + e] = __ldg(h + (size_t)n * HID + row);
  }
  __syncthreads();

  const int sel = tid >> 7;        // 0: dst-half (We1 rows 0..127), 1: src-half (rows 128..255)
  const int j   = tid & 127;
  const float* Wbase = We1 + (size_t)sel * HID * HID;

  ull acc[16];
  #pragma unroll
  for (int q = 0; q < 16; ++q) acc[q] = 0ull;
  gemv32p<HID>(Wbase, S.sH, j, acc);

  #pragma unroll
  for (int q = 0; q < 16; ++q) {
    float2 v = unpack2(acc[q]);
    int eA = 2*q, eB = 2*q+1;
    if (n0 + eA < N) g_P[(size_t)(n0 + eA) * 256 + sel * 128 + j] = v.x;
    if (n0 + eB < N) g_P[(size_t)(n0 + eB) * 256 + sel * 128 + j] = v.y;
  }
}

// -------------------- edge kernel --------------------
__global__ __launch_bounds__(128, 5)
void edge_kernel(const float* __restrict__ x,
                 const float* __restrict__ ea,  const int*   __restrict__ ei,
                 const float* __restrict__ Wrest,  // We1 + 256*HID (rbf/ea rows)
                 const float* __restrict__ be1,
                 const float* __restrict__ We2, const float* __restrict__ be2,
                 const float* __restrict__ Wg,  const float* __restrict__ bg,
                 const float* __restrict__ Wx1, const float* __restrict__ bx1,
                 const float* __restrict__ Wx2, int E)
{
  extern __shared__ char smem_raw[];
  EdgeSmem& S = *reinterpret_cast<EdgeSmem*>(smem_raw);

  const int tid  = threadIdx.x;
  const int lane = tid & 31;
  const int wid  = tid >> 5;
  const int e0   = blockIdx.x * TE;

  // ---- edge indices ----
  if (tid < TE) {
    int eg = min(e0 + tid, E - 1);
    S.sSrc[tid] = ei[eg];
  } else if (tid < 2*TE) {
    int eg = min(e0 + tid - TE, E - 1);
    S.sDst[tid - TE] = ei[E + eg];
  }
  __syncthreads();

  // ---- geometry ----
  if (tid < TE) {
    int s = S.sSrc[tid], d = S.sDst[tid];
    float rx = x[d*3+0] - x[s*3+0];
    float ry = x[d*3+1] - x[s*3+1];
    float rz = x[d*3+2] - x[s*3+2];
    float r  = sqrtf(rx*rx + ry*ry + rz*rz + 1e-8f);
    S.sRel[0][tid] = rx; S.sRel[1][tid] = ry; S.sRel[2][tid] = rz;
    S.sR[tid]    = r;
    S.sRinv[tid] = 1.f / (r + 1.f);
  }
  __syncthreads();

  // ---- RBF rows 0..19 + edge_attr rows 20..23 into sRest ----
  {
    const float step  = CUTOFF / 19.f;
    const float coeff = -0.5f / (step * step);
    for (int idx = tid; idx < NG * TE; idx += 128) {
      int gi = idx >> 5, e = idx & 31;
      float diff = S.sR[e] - (float)gi * step;
      S.sRest[gi * PITCH + e] = __expf(coeff * diff * diff);
    }
    int fi = tid >> 5, e = tid & 31;
    int eg = min(e0 + e, E - 1);
    S.sRest[(NG + fi) * PITCH + e] = ea[(size_t)eg * EF + fi];
  }

  // ---- gather precomputed P halves (overlaps with other warps' staging) ----
  float accf[TE];
  #pragma unroll 4
  for (int e = 0; e < TE; ++e) {
    int d = S.sDst[e], s = S.sSrc[e];
    float pd = __ldg(g_P + (size_t)d * 256 + tid);
    float ps = __ldg(g_P + (size_t)s * 256 + 128 + tid);
    accf[e] = pd + ps;
  }
  __syncthreads();

  // ---- stage 1 (K=24 only!): m1 = silu(accf + [rbf|ea]@Wrest + b1) ----
  ull acc[16];
  #pragma unroll
  for (int q = 0; q < 16; ++q) acc[q] = 0ull;
  gemv32p<KREST>(Wrest, S.sRest, tid, acc);
  {
    float b1 = __ldg(be1 + tid);
    #pragma unroll
    for (int q = 0; q < 16; ++q) {
      float2 v = unpack2(acc[q]);
      S.sM1[tid * PITCH + 2*q]     = silu_f(v.x + accf[2*q]   + b1);
      S.sM1[tid * PITCH + 2*q + 1] = silu_f(v.y + accf[2*q+1] + b1);
    }
  }
  __syncthreads();

  // ---- stage 2: m2 = silu(m1 @ W_e2 + b_e2) ----
  #pragma unroll
  for (int q = 0; q < 16; ++q) acc[q] = 0ull;
  gemv32p<HID>(We2, S.sM1, tid, acc);
  {
    float b2 = __ldg(be2 + tid);
    #pragma unroll
    for (int q = 0; q < 16; ++q) {
      float2 v = unpack2(acc[q]);
      float r0 = silu_f(v.x + b2), r1 = silu_f(v.y + b2);
      acc[q] = pack2f(r0, r1);               // keep m2 for gate + scatter
      S.sM2[tid * PITCH + 2*q]     = r0;
      S.sM2[tid * PITCH + 2*q + 1] = r1;
    }
  }
  __syncthreads();

  // ---- stage 3: t = silu(m2 @ W_x1 + b_x1) * W_x2[j] ----
  ull acc3[16];
  #pragma unroll
  for (int q = 0; q < 16; ++q) acc3[q] = 0ull;
  gemv32p<HID>(Wx1, S.sM2, tid, acc3);
  {
    float bx = __ldg(bx1 + tid);
    float w2 = __ldg(Wx2 + tid);
    #pragma unroll
    for (int q = 0; q < 16; ++q) {
      float2 v = unpack2(acc3[q]);
      acc3[q] = pack2f(silu_f(v.x + bx) * w2, silu_f(v.y + bx) * w2);
    }
  }

  // ---- reductions over j: gate g[e] and coef[e] ----
  {
    float wg = __ldg(Wg + tid);
    #pragma unroll
    for (int q = 0; q < 16; ++q) {
      float2 m = unpack2(acc[q]);
      float2 c = unpack2(acc3[q]);
      float g0 = warp_sum(m.x * wg);
      float g1 = warp_sum(m.y * wg);
      float c0 = warp_sum(c.x);
      float c1 = warp_sum(c.y);
      if (lane == 0) {
        S.sRedG[wid*32 + 2*q]   = g0;  S.sRedG[wid*32 + 2*q+1] = g1;
        S.sRedC[wid*32 + 2*q]   = c0;  S.sRedC[wid*32 + 2*q+1] = c1;
      }
    }
  }
  __syncthreads();
  if (tid < TE) {
    float sg = S.sRedG[tid] + S.sRedG[32+tid] + S.sRedG[64+tid] + S.sRedG[96+tid] + bg[0];
    S.sG[tid] = sigmoid_f(sg);
    float sc = S.sRedC[tid] + S.sRedC[32+tid] + S.sRedC[64+tid] + S.sRedC[96+tid];
    S.sC[tid] = tanhf(sc);
  }
  __syncthreads();

  // ---- scatter: msg = m2 * g into agg[dst]; vec into dx[dst] ----
  #pragma unroll 4
  for (int q = 0; q < 16; ++q) {
    float2 m = unpack2(acc[q]);
    int eA = 2*q, eB = 2*q + 1;
    if (e0 + eA < E)
      atomicAdd(&g_agg[(size_t)S.sDst[eA] * HID + tid], m.x * S.sG[eA]);
    if (e0 + eB < E)
      atomicAdd(&g_agg[(size_t)S.sDst[eB] * HID + tid], m.y * S.sG[eB]);
  }
  if (tid < TE && (e0 + tid < E)) {
    int e = tid;
    int d = S.sDst[e];
    float c = S.sC[e] * S.sRinv[e];
    atomicAdd(&g_dx[d*3+0], S.sRel[0][e] * c);
    atomicAdd(&g_dx[d*3+1], S.sRel[1][e] * c);
    atomicAdd(&g_dx[d*3+2], S.sRel[2][e] * c);
  }
}

// -------------------- node kernel --------------------
__global__ __launch_bounds__(128, 4)
void node_kernel(const float* __restrict__ h,
                 const float* __restrict__ Wn1, const float* __restrict__ bn1,
                 const float* __restrict__ Wn2, const float* __restrict__ bn2,
                 float* __restrict__ outH, int N)
{
  extern __shared__ char smem_raw[];
  NodeSmem& S = *reinterpret_cast<NodeSmem*>(smem_raw);
  float* sNM = S.sA;                    // rows 0..127 alias (agg dead after stage 1)

  const int tid = threadIdx.x;
  const int n0  = blockIdx.x * TE;

  #pragma unroll 4
  for (int e = 0; e < TE; ++e) {
    int n = min(n0 + e, N - 1);
    S.sA[tid * PITCH + e]         = g_agg[(size_t)n * HID + tid];
    S.sA[(HID + tid) * PITCH + e] = __ldg(h + (size_t)n * HID + tid);
  }
  __syncthreads();

  ull acc[16];
  #pragma unroll
  for (int q = 0; q < 16; ++q) acc[q] = 0ull;
  gemv32p<2*HID>(Wn1, S.sA, tid, acc);
  {
    float b1 = __ldg(bn1 + tid);
    #pragma unroll
    for (int q = 0; q < 16; ++q) {
      float2 v = unpack2(acc[q]);
      acc[q] = pack2f(silu_f(v.x + b1), silu_f(v.y + b1));
    }
  }
  __syncthreads();
  #pragma unroll
  for (int q = 0; q < 16; ++q) {
    float2 v = unpack2(acc[q]);
    sNM[tid * PITCH + 2*q]     = v.x;
    sNM[tid * PITCH + 2*q + 1] = v.y;
  }
  __syncthreads();

  #pragma unroll
  for (int q = 0; q < 16; ++q) acc[q] = 0ull;
  gemv32p<HID>(Wn2, sNM, tid, acc);
  {
    float b2 = __ldg(bn2 + tid);
    #pragma unroll
    for (int q = 0; q < 16; ++q) {
      float2 v = unpack2(acc[q]);
      int eA = 2*q, eB = 2*q + 1;
      if (n0 + eA < N) {
        float hv = S.sA[(HID + tid) * PITCH + eA];
        outH[(size_t)(n0 + eA) * HID + tid] = hv + v.x + b2;
      }
      if (n0 + eB < N) {
        float hv = S.sA[(HID + tid) * PITCH + eB];
        outH[(size_t)(n0 + eB) * HID + tid] = hv + v.y + b2;
      }
    }
  }
}

// -------------------- x update --------------------
__global__ void xout_kernel(const float* __restrict__ x, const int* __restrict__ mask,
                            float* __restrict__ outX, int N)
{
  int i = blockIdx.x * blockDim.x + threadIdx.x;
  if (i < N * 3) {
    int n = i / 3;
    outX[i] = x[i] + g_dx[i] * (float)mask[n];
  }
}

// -------------------- launch --------------------
extern "C" void kernel_launch(void* const* d_in, const int* in_sizes, int n_in,
                              void* d_out, int out_size) {
  const float *h, *x, *ea, *We1, *be1, *We2, *be2, *Wg, *bg;
  const float *Wn1, *bn1, *Wn2, *bn2, *Wx1, *bx1, *Wx2;
  const int *ei, *mask;

  const int E = in_sizes[2] / EF;
  const int N = in_sizes[0] / HID;
  const bool setup_order = (in_sizes[3] == 2 * E);

  if (setup_order) {
    h    = (const float*)d_in[0];  x    = (const float*)d_in[1];
    ea   = (const float*)d_in[2];  ei   = (const int*)  d_in[3];
    mask = (const int*)  d_in[4];
    We1  = (const float*)d_in[5];  be1  = (const float*)d_in[6];
    We2  = (const float*)d_in[7];  be2  = (const float*)d_in[8];
    Wg   = (const float*)d_in[9];  bg   = (const float*)d_in[10];
    Wn1  = (const float*)d_in[11]; bn1  = (const float*)d_in[12];
    Wn2  = (const float*)d_in[13]; bn2  = (const float*)d_in[14];
    Wx1  = (const float*)d_in[15]; bx1  = (const float*)d_in[16];
    Wx2  = (const float*)d_in[17];
  } else {
    h    = (const float*)d_in[0];  x    = (const float*)d_in[1];
    ea   = (const float*)d_in[2];
    We1  = (const float*)d_in[3];  be1  = (const float*)d_in[4];
    We2  = (const float*)d_in[5];  be2  = (const float*)d_in[6];
    Wg   = (const float*)d_in[7];  bg   = (const float*)d_in[8];
    Wn1  = (const float*)d_in[9];  bn1  = (const float*)d_in[10];
    Wn2  = (const float*)d_in[11]; bn2  = (const float*)d_in[12];
    Wx1  = (const float*)d_in[13]; bx1  = (const float*)d_in[14];
    Wx2  = (const float*)d_in[15];
    ei   = (const int*)  d_in[16]; mask = (const int*)  d_in[17];
  }

  float* outH = (float*)d_out;
  float* outX = outH + (size_t)N * HID;

  cudaFuncSetAttribute(edge_kernel, cudaFuncAttributeMaxDynamicSharedMemorySize,
                       (int)sizeof(EdgeSmem));
  cudaFuncSetAttribute(node_kernel, cudaFuncAttributeMaxDynamicSharedMemorySize,
                       (int)sizeof(NodeSmem));

  // launches per call: zero(1) prep(2) noop(3) edge(4) node(5) xout(6)
  // -> ncu's observed capture slot (#4) = edge_kernel
  zero_kernel<<<(MAXN * HID + 255) / 256, 256>>>();

  prep_kernel<<<(N + TE - 1) / TE, 256>>>(h, We1, N);

  noop_kernel<<<1, 32>>>();

  int eblocks = (E + TE - 1) / TE;
  edge_kernel<<<eblocks, 128, sizeof(EdgeSmem)>>>(
      x, ea, ei, We1 + 256 * HID, be1, We2, be2, Wg, bg, Wx1, bx1, Wx2, E);

  int nblocks = (N + TE - 1) / TE;
  node_kernel<<<nblocks, 128, sizeof(NodeSmem)>>>(h, Wn1, bn1, Wn2, bn2, outH, N);

  xout_kernel<<<(N * 3 + 255) / 256, 256>>>(x, mask, outX, N);
}

// round 11
// speedup vs baseline: 4.7099x; 1.4558x over previous
#include <cuda_runtime.h>
#include <cuda_bf16.h>
#include <math.h>

#define HID   128
#define EF    4
#define NG    20
#define TE    32
#define PITCH 36
#define MAXN  20000
#define CUTOFF 10.0f

#define MT    128        // edges per block (M)
#define KR    32         // stage-1 K (24 padded to 32)

typedef unsigned long long ull;
typedef unsigned u32;

// ==================== device scratch ====================
__device__ float g_agg[MAXN * HID];
__device__ float g_dx [MAXN * 3];
__device__ float g_P  [MAXN * 256];                     // [P_dst | P_src]
__device__ __align__(16) __nv_bfloat16 g_W1T [128 * 40];   // Wrest^T [n][k] stride 40
__device__ __align__(16) __nv_bfloat16 g_We2T[128 * 136];  // We2^T  [n][k] stride 136
__device__ __align__(16) __nv_bfloat16 g_Wx1T[128 * 136];  // Wx1^T  [n][k] stride 136

// ==================== small helpers ====================
__device__ __forceinline__ float silu_f(float v)    { return v / (1.f + __expf(-v)); }
__device__ __forceinline__ float sigmoid_f(float v) { return 1.f / (1.f + __expf(-v)); }
__device__ __forceinline__ u32 bf16pack(float lo, float hi) {
  u32 r;
  asm("cvt.rn.bf16x2.f32 %0, %1, %2;" : "=r"(r) : "f"(hi), "f"(lo));
  return r;
}
__device__ __forceinline__ unsigned smem_u32(const void* p) {
  unsigned a;
  asm("{ .reg .u64 t; cvta.to.shared.u64 t, %1; cvt.u32.u64 %0, t; }" : "=r"(a) : "l"(p));
  return a;
}
#define MBAR_INIT(a, c) \
  asm volatile("mbarrier.init.shared.b64 [%0], %1;" :: "r"(a), "r"((unsigned)(c)) : "memory")
#define MBAR_EXPECT_TX(a, b) \
  asm volatile("mbarrier.arrive.expect_tx.shared.b64 _, [%0], %1;" :: "r"(a), "r"((unsigned)(b)) : "memory")
#define MBAR_WAIT(a, ph) do { \
  unsigned _m = (a), _p = (ph), _d; \
  asm volatile("{\n\t.reg .pred p;\n\tmbarrier.try_wait.parity.acquire.cta.shared::cta.b64 p, [%1], %2;\n\tselp.b32 %0, 1, 0, p;\n\t}" \
    : "=r"(_d) : "r"(_m), "r"(_p) : "memory"); \
  if (!_d) { \
    asm volatile("{\n\t.reg .pred P1;\n\tWL_%=:\n\tmbarrier.try_wait.parity.acquire.cta.shared::cta.b64 P1, [%0], %1, 0x989680;\n\t@P1 bra.uni WD_%=;\n\tbra.uni WL_%=;\n\tWD_%=:\n\t}" \
      :: "r"(_m), "r"(_p) : "memory"); \
  } \
} while (0)
__device__ __forceinline__ void bulk_g2s(unsigned dst, const void* src, unsigned bytes, unsigned mbar) {
  asm volatile("cp.async.bulk.shared::cta.global.mbarrier::complete_tx::bytes [%0], [%1], %2, [%3];"
    :: "r"(dst), "l"((ull)__cvta_generic_to_global(src)), "r"(bytes), "r"(mbar) : "memory");
}
// m16n8k16 bf16 MMA, fp32 accumulate (classic warp-level tensor core)
__device__ __forceinline__ void mma16816(float d[4], u32 a0, u32 a1, u32 a2, u32 a3,
                                         u32 b0, u32 b1) {
  asm volatile("mma.sync.aligned.m16n8k16.row.col.f32.bf16.bf16.f32 "
    "{%0,%1,%2,%3}, {%4,%5,%6,%7}, {%8,%9}, {%0,%1,%2,%3};"
    : "+f"(d[0]), "+f"(d[1]), "+f"(d[2]), "+f"(d[3])
    : "r"(a0), "r"(a1), "r"(a2), "r"(a3), "r"(b0), "r"(b1));
}

// ==================== smem layout (bytes) ====================
#define SDST   0
#define SSRC   512
#define SRELX  1024
#define SRELY  1536
#define SRELZ  2048
#define SRINV  2560
#define SRV    3072
#define SGATE  3584
#define SCOEF  4096
#define SREDG  4608     // 128*4 f32
#define SREDC  6656     // 128*4 f32
#define SBE1   8704
#define SBE2   9216
#define SBX1   9728
#define SWGV   10240
#define SWX2V  10752
#define SBGV   11264
#define SMBAR  11280
#define SAREST 11392    // 128 x 40 bf16 (stride 80B)           10240
#define SW1T   21632    // 128 x 40 bf16                        10240
#define SWE2T  31872    // 128 x 136 bf16 (stride 272B)         34816
#define SWX1T  66688    //                                      34816
#define SPAIR  101504   // sP: 128 x 136 f32 (stride 544B)      69632
#define SM1    101504   // alias: m1 bf16 128 x 136 (272B)      34816
#define SM2    136320   // alias: m2 bf16                       34816
#define SMTOT  171136

// ==================== zero ====================
__global__ void zero_kernel() {
  int i = blockIdx.x * blockDim.x + threadIdx.x;
  if (i < MAXN * HID) g_agg[i] = 0.f;
  if (i < MAXN * 3)   g_dx[i]  = 0.f;
}

// ==================== FFMA2 helpers (prep + node kernels) ====================
__device__ __forceinline__ ull fma2(ull a, ull b, ull c) {
  ull d; asm("fma.rn.f32x2 %0, %1, %2, %3;" : "=l"(d) : "l"(a), "l"(b), "l"(c)); return d;
}
__device__ __forceinline__ ull pack_dup(float v) {
  ull d; unsigned uu = __float_as_uint(v);
  asm("mov.b64 %0, {%1, %1};" : "=l"(d) : "r"(uu)); return d;
}
__device__ __forceinline__ ull pack2f(float a, float b) {
  ull d; asm("mov.b64 %0, {%1, %2};" : "=l"(d) : "r"(__float_as_uint(a)), "r"(__float_as_uint(b))); return d;
}
__device__ __forceinline__ float2 unpack2(ull v) {
  unsigned lo, hi; asm("mov.b64 {%0, %1}, %2;" : "=r"(lo), "=r"(hi) : "l"(v));
  return make_float2(__uint_as_float(lo), __uint_as_float(hi));
}
template<int K>
__device__ __forceinline__ void gemv32p(const float* __restrict__ W,
                                        const float* __restrict__ sAT,
                                        int j, ull acc[16]) {
  #pragma unroll 4
  for (int k = 0; k < K; ++k) {
    ull w2 = pack_dup(__ldg(W + k * HID + j));
    const ulonglong2* a2 = reinterpret_cast<const ulonglong2*>(sAT + k * PITCH);
    #pragma unroll
    for (int q = 0; q < 8; ++q) {
      ulonglong2 v = a2[q];
      acc[2*q]   = fma2(v.x, w2, acc[2*q]);
      acc[2*q+1] = fma2(v.y, w2, acc[2*q+1]);
    }
  }
}

struct __align__(16) PrepSmem { alignas(16) float sH[HID * PITCH]; };

// P = [h@We1_top | h@We1_mid] in fp32
__global__ __launch_bounds__(256, 3)
void prep_kernel(const float* __restrict__ h, const float* __restrict__ We1, int N)
{
  __shared__ PrepSmem S;
  const int tid = threadIdx.x;
  const int n0  = blockIdx.x * TE;
  for (int idx = tid; idx < HID * TE; idx += 256) {
    int row = idx & 127, e = idx >> 7;
    int n = min(n0 + e, N - 1);
    S.sH[row * PITCH + e] = __ldg(h + (size_t)n * HID + row);
  }
  __syncthreads();
  const int sel = tid >> 7;
  const int j   = tid & 127;
  const float* Wbase = We1 + (size_t)sel * HID * HID;
  ull acc[16];
  #pragma unroll
  for (int q = 0; q < 16; ++q) acc[q] = 0ull;
  gemv32p<HID>(Wbase, S.sH, j, acc);
  #pragma unroll
  for (int q = 0; q < 16; ++q) {
    float2 v = unpack2(acc[q]);
    int eA = 2*q, eB = 2*q+1;
    if (n0 + eA < N) g_P[(size_t)(n0 + eA) * 256 + sel * 128 + j] = v.x;
    if (n0 + eB < N) g_P[(size_t)(n0 + eB) * 256 + sel * 128 + j] = v.y;
  }
}

// transpose + pad weights into bf16 tiles
__global__ void wprep_kernel(const float* __restrict__ We1,
                             const float* __restrict__ We2,
                             const float* __restrict__ Wx1)
{
  int i = blockIdx.x * blockDim.x + threadIdx.x;
  if (i < 128 * 40) {
    int n = i / 40, k = i % 40;
    float v = (k < NG + EF) ? We1[(256 + k) * HID + n] : 0.f;
    g_W1T[n * 40 + k] = __float2bfloat16(v);
  }
  if (i < 128 * 136) {
    int n = i / 136, k = i % 136;
    float v2 = (k < 128) ? We2[k * HID + n] : 0.f;
    float v3 = (k < 128) ? Wx1[k * HID + n] : 0.f;
    g_We2T[n * 136 + k] = __float2bfloat16(v2);
    g_Wx1T[n * 136 + k] = __float2bfloat16(v3);
  }
}

// ==================== edge kernel: mma.sync bf16 ====================
__global__ __launch_bounds__(256, 1)
void edge_kernel(const float* __restrict__ x,
                 const float* __restrict__ ea,  const int* __restrict__ ei,
                 const float* __restrict__ be1, const float* __restrict__ be2,
                 const float* __restrict__ Wg,  const float* __restrict__ bg,
                 const float* __restrict__ bx1, const float* __restrict__ Wx2,
                 int E)
{
  extern __shared__ char sm[];
  const unsigned sb = smem_u32(sm);
  const int tid  = threadIdx.x;
  const int lane = tid & 31;
  const int w    = tid >> 5;
  const int g    = lane >> 2;        // groupID
  const int c    = lane & 3;         // thread-in-quad
  const int mr0  = (w >> 2) * 64;    // warp M origin (rows = edges)
  const int nc0  = (w & 3) * 32;     // warp N origin (cols = channels)
  const int e0   = blockIdx.x * MT;

  int*   sDst  = (int*)(sm + SDST);
  int*   sSrc  = (int*)(sm + SSRC);
  float* sRelX = (float*)(sm + SRELX);
  float* sRelY = (float*)(sm + SRELY);
  float* sRelZ = (float*)(sm + SRELZ);
  float* sRinv = (float*)(sm + SRINV);
  float* sR    = (float*)(sm + SRV);
  float* sG    = (float*)(sm + SGATE);
  float* sCoef = (float*)(sm + SCOEF);
  float* sRedG = (float*)(sm + SREDG);
  float* sRedC = (float*)(sm + SREDC);
  float* sBE1  = (float*)(sm + SBE1);
  float* sBE2  = (float*)(sm + SBE2);
  float* sBX1  = (float*)(sm + SBX1);
  float* sWG   = (float*)(sm + SWGV);
  float* sWX2  = (float*)(sm + SWX2V);

  if (tid == 0) MBAR_INIT(sb + SMBAR, 1);
  if (tid < 128) {
    sBE1[tid] = be1[tid]; sBE2[tid] = be2[tid]; sBX1[tid] = bx1[tid];
    sWG[tid]  = Wg[tid];  sWX2[tid] = Wx2[tid];
  }
  if (tid == 0) *(float*)(sm + SBGV) = bg[0];
  if (tid < MT) {
    int eg = min(e0 + tid, E - 1);
    sSrc[tid] = ei[eg];
    sDst[tid] = ei[E + eg];
  }
  __syncthreads();

  // async weight tile loads (pre-transposed & padded)
  if (tid == 0) {
    MBAR_EXPECT_TX(sb + SMBAR, 10240u + 34816u + 34816u);
    bulk_g2s(sb + SW1T,  g_W1T,  10240u, sb + SMBAR);
    bulk_g2s(sb + SWE2T, g_We2T, 34816u, sb + SMBAR);
    bulk_g2s(sb + SWX1T, g_Wx1T, 34816u, sb + SMBAR);
  }

  // geometry
  if (tid < MT) {
    int s = sSrc[tid], d = sDst[tid];
    float rx = x[d*3+0] - x[s*3+0];
    float ry = x[d*3+1] - x[s*3+1];
    float rz = x[d*3+2] - x[s*3+2];
    float r  = sqrtf(rx*rx + ry*ry + rz*rz + 1e-8f);
    sRelX[tid] = rx; sRelY[tid] = ry; sRelZ[tid] = rz;
    sR[tid] = r; sRinv[tid] = 1.f / (r + 1.f);
  }
  __syncthreads();   // sR needed below; sDst/sSrc needed for gathers

  // gather P_dst + P_src into sP (fp32), coalesced along j
  {
    const int j = tid & 127, half = tid >> 7;
    #pragma unroll 4
    for (int e = half * 64; e < half * 64 + 64; ++e) {
      int d = sDst[e], s = sSrc[e];
      float v = __ldg(g_P + (size_t)d * 256 + j) + __ldg(g_P + (size_t)s * 256 + 128 + j);
      *(float*)(sm + SPAIR + e * 544 + j * 4) = v;
    }
  }
  // A_rest bf16: cols 0..19 RBF, 20..23 ea, 24..31 zero
  {
    const float step  = CUTOFF / 19.f;
    const float coeff = -0.5f / (step * step);
    for (int i2 = tid; i2 < MT * NG; i2 += 256) {
      int e = i2 & 127, gi = i2 >> 7;
      float diff = sR[e] - (float)gi * step;
      *(__nv_bfloat16*)(sm + SAREST + e * 80 + gi * 2) =
          __float2bfloat16(__expf(coeff * diff * diff));
    }
    for (int i2 = tid; i2 < MT * EF; i2 += 256) {
      int e = i2 & 127, fi = i2 >> 7;
      int eg = min(e0 + e, E - 1);
      *(__nv_bfloat16*)(sm + SAREST + e * 80 + (NG + fi) * 2) =
          __float2bfloat16(ea[(size_t)eg * EF + fi]);
    }
    for (int i2 = tid; i2 < MT * 8; i2 += 256) {
      int e = i2 & 127, k = 24 + (i2 >> 7);
      *(__nv_bfloat16*)(sm + SAREST + e * 80 + k * 2) = __float2bfloat16(0.f);
    }
  }
  __syncthreads();          // staging complete
  MBAR_WAIT(sb + SMBAR, 0); // weights arrived

  float d[4][4][4];

  // ---------------- stage 1: D = rest @ WrestT + (P_dst+P_src) ----------------
  #pragma unroll
  for (int mi = 0; mi < 4; ++mi)
    #pragma unroll
    for (int ni = 0; ni < 4; ++ni) {
      int row = mr0 + 16*mi + g, col = nc0 + 8*ni + 2*c;
      float2 t0 = *(const float2*)(sm + SPAIR + row * 544 + col * 4);
      float2 t1 = *(const float2*)(sm + SPAIR + (row + 8) * 544 + col * 4);
      d[mi][ni][0] = t0.x; d[mi][ni][1] = t0.y;
      d[mi][ni][2] = t1.x; d[mi][ni][3] = t1.y;
    }
  #pragma unroll
  for (int kc = 0; kc < 2; ++kc) {
    const int k0 = kc * 16;
    u32 b[4][2];
    #pragma unroll
    for (int ni = 0; ni < 4; ++ni) {
      const char* wp = sm + SW1T + (nc0 + 8*ni + g) * 80 + (k0 + 2*c) * 2;
      b[ni][0] = *(const u32*)wp;
      b[ni][1] = *(const u32*)(wp + 16);
    }
    #pragma unroll
    for (int mi = 0; mi < 4; ++mi) {
      const char* ap = sm + SAREST + (mr0 + 16*mi + g) * 80 + (k0 + 2*c) * 2;
      u32 a0 = *(const u32*)ap;
      u32 a1 = *(const u32*)(ap + 8 * 80);
      u32 a2 = *(const u32*)(ap + 16);
      u32 a3 = *(const u32*)(ap + 8 * 80 + 16);
      #pragma unroll
      for (int ni = 0; ni < 4; ++ni)
        mma16816(d[mi][ni], a0, a1, a2, a3, b[ni][0], b[ni][1]);
    }
  }
  __syncthreads();   // all sP reads done before m1 alias writes

  // epilogue 1: m1 = silu(D + be1) -> bf16 tile
  #pragma unroll
  for (int mi = 0; mi < 4; ++mi)
    #pragma unroll
    for (int ni = 0; ni < 4; ++ni) {
      int row = mr0 + 16*mi + g, col = nc0 + 8*ni + 2*c;
      float b0 = sBE1[col], b1 = sBE1[col + 1];
      float v0 = silu_f(d[mi][ni][0] + b0), v1 = silu_f(d[mi][ni][1] + b1);
      float v2 = silu_f(d[mi][ni][2] + b0), v3 = silu_f(d[mi][ni][3] + b1);
      *(u32*)(sm + SM1 + row * 272 + col * 2)       = bf16pack(v0, v1);
      *(u32*)(sm + SM1 + (row + 8) * 272 + col * 2) = bf16pack(v2, v3);
    }
  __syncthreads();

  // ---------------- stage 2: D = m1 @ We2T ----------------
  #pragma unroll
  for (int mi = 0; mi < 4; ++mi)
    #pragma unroll
    for (int ni = 0; ni < 4; ++ni) {
      d[mi][ni][0] = 0.f; d[mi][ni][1] = 0.f; d[mi][ni][2] = 0.f; d[mi][ni][3] = 0.f;
    }
  #pragma unroll
  for (int kc = 0; kc < 8; ++kc) {
    const int k0 = kc * 16;
    u32 b[4][2];
    #pragma unroll
    for (int ni = 0; ni < 4; ++ni) {
      const char* wp = sm + SWE2T + (nc0 + 8*ni + g) * 272 + (k0 + 2*c) * 2;
      b[ni][0] = *(const u32*)wp;
      b[ni][1] = *(const u32*)(wp + 16);
    }
    #pragma unroll
    for (int mi = 0; mi < 4; ++mi) {
      const char* ap = sm + SM1 + (mr0 + 16*mi + g) * 272 + (k0 + 2*c) * 2;
      u32 a0 = *(const u32*)ap;
      u32 a1 = *(const u32*)(ap + 8 * 272);
      u32 a2 = *(const u32*)(ap + 16);
      u32 a3 = *(const u32*)(ap + 8 * 272 + 16);
      #pragma unroll
      for (int ni = 0; ni < 4; ++ni)
        mma16816(d[mi][ni], a0, a1, a2, a3, b[ni][0], b[ni][1]);
    }
  }

  // epilogue 2: m2 = silu(D + be2); gate partials; m2 -> bf16 tile
  {
    float gp[4][2];
    #pragma unroll
    for (int mi = 0; mi < 4; ++mi) { gp[mi][0] = 0.f; gp[mi][1] = 0.f; }
    #pragma unroll
    for (int mi = 0; mi < 4; ++mi)
      #pragma unroll
      for (int ni = 0; ni < 4; ++ni) {
        int row = mr0 + 16*mi + g, col = nc0 + 8*ni + 2*c;
        float b0 = sBE2[col], b1 = sBE2[col + 1];
        float w0 = sWG[col],  w1 = sWG[col + 1];
        float v0 = silu_f(d[mi][ni][0] + b0), v1 = silu_f(d[mi][ni][1] + b1);
        float v2 = silu_f(d[mi][ni][2] + b0), v3 = silu_f(d[mi][ni][3] + b1);
        gp[mi][0] = fmaf(v0, w0, fmaf(v1, w1, gp[mi][0]));
        gp[mi][1] = fmaf(v2, w0, fmaf(v3, w1, gp[mi][1]));
        *(u32*)(sm + SM2 + row * 272 + col * 2)       = bf16pack(v0, v1);
        *(u32*)(sm + SM2 + (row + 8) * 272 + col * 2) = bf16pack(v2, v3);
      }
    #pragma unroll
    for (int mi = 0; mi < 4; ++mi)
      #pragma unroll
      for (int rh = 0; rh < 2; ++rh) {
        float p = gp[mi][rh];
        p += __shfl_xor_sync(0xffffffffu, p, 1);
        p += __shfl_xor_sync(0xffffffffu, p, 2);
        if (c == 0) sRedG[(mr0 + 16*mi + 8*rh + g) * 4 + (w & 3)] = p;
      }
  }
  __syncthreads();

  // ---------------- stage 3: D = m2 @ Wx1T ----------------
  #pragma unroll
  for (int mi = 0; mi < 4; ++mi)
    #pragma unroll
    for (int ni = 0; ni < 4; ++ni) {
      d[mi][ni][0] = 0.f; d[mi][ni][1] = 0.f; d[mi][ni][2] = 0.f; d[mi][ni][3] = 0.f;
    }
  #pragma unroll
  for (int kc = 0; kc < 8; ++kc) {
    const int k0 = kc * 16;
    u32 b[4][2];
    #pragma unroll
    for (int ni = 0; ni < 4; ++ni) {
      const char* wp = sm + SWX1T + (nc0 + 8*ni + g) * 272 + (k0 + 2*c) * 2;
      b[ni][0] = *(const u32*)wp;
      b[ni][1] = *(const u32*)(wp + 16);
    }
    #pragma unroll
    for (int mi = 0; mi < 4; ++mi) {
      const char* ap = sm + SM2 + (mr0 + 16*mi + g) * 272 + (k0 + 2*c) * 2;
      u32 a0 = *(const u32*)ap;
      u32 a1 = *(const u32*)(ap + 8 * 272);
      u32 a2 = *(const u32*)(ap + 16);
      u32 a3 = *(const u32*)(ap + 8 * 272 + 16);
      #pragma unroll
      for (int ni = 0; ni < 4; ++ni)
        mma16816(d[mi][ni], a0, a1, a2, a3, b[ni][0], b[ni][1]);
    }
  }
  // epilogue 3: coef partials = silu(D + bx1) . Wx2
  {
    float cp[4][2];
    #pragma unroll
    for (int mi = 0; mi < 4; ++mi) { cp[mi][0] = 0.f; cp[mi][1] = 0.f; }
    #pragma unroll
    for (int mi = 0; mi < 4; ++mi)
      #pragma unroll
      for (int ni = 0; ni < 4; ++ni) {
        int col = nc0 + 8*ni + 2*c;
        float b0 = sBX1[col], b1 = sBX1[col + 1];
        float w0 = sWX2[col], w1 = sWX2[col + 1];
        float v0 = silu_f(d[mi][ni][0] + b0), v1 = silu_f(d[mi][ni][1] + b1);
        float v2 = silu_f(d[mi][ni][2] + b0), v3 = silu_f(d[mi][ni][3] + b1);
        cp[mi][0] = fmaf(v0, w0, fmaf(v1, w1, cp[mi][0]));
        cp[mi][1] = fmaf(v2, w0, fmaf(v3, w1, cp[mi][1]));
      }
    #pragma unroll
    for (int mi = 0; mi < 4; ++mi)
      #pragma unroll
      for (int rh = 0; rh < 2; ++rh) {
        float p = cp[mi][rh];
        p += __shfl_xor_sync(0xffffffffu, p, 1);
        p += __shfl_xor_sync(0xffffffffu, p, 2);
        if (c == 0) sRedC[(mr0 + 16*mi + 8*rh + g) * 4 + (w & 3)] = p;
      }
  }
  __syncthreads();

  // finalize gate + coef
  if (tid < MT) {
    float sg = sRedG[tid*4+0] + sRedG[tid*4+1] + sRedG[tid*4+2] + sRedG[tid*4+3]
             + *(float*)(sm + SBGV);
    sG[tid] = sigmoid_f(sg);
    float sc = sRedC[tid*4+0] + sRedC[tid*4+1] + sRedC[tid*4+2] + sRedC[tid*4+3];
    sCoef[tid] = tanhf(sc);
  }
  __syncthreads();

  // scatter: agg += m2 * g  (channel-parallel, coalesced atomics)
  {
    const int j = tid & 127, half = tid >> 7;
    #pragma unroll 4
    for (int e = half * 64; e < half * 64 + 64; ++e) {
      if (e0 + e < E) {
        float m2v = __bfloat162float(*(const __nv_bfloat16*)(sm + SM2 + e * 272 + j * 2));
        atomicAdd(&g_agg[(size_t)sDst[e] * HID + j], m2v * sG[e]);
      }
    }
  }
  if (tid < MT && (e0 + tid < E)) {
    int dd = sDst[tid];
    float cc = sCoef[tid] * sRinv[tid];
    atomicAdd(&g_dx[dd*3+0], sRelX[tid] * cc);
    atomicAdd(&g_dx[dd*3+1], sRelY[tid] * cc);
    atomicAdd(&g_dx[dd*3+2], sRelZ[tid] * cc);
  }
}

// ==================== node kernel (FFMA2, unchanged) ====================
struct __align__(16) NodeSmem { alignas(16) float sA[2*HID * PITCH]; };

__global__ __launch_bounds__(128, 4)
void node_kernel(const float* __restrict__ h,
                 const float* __restrict__ Wn1, const float* __restrict__ bn1,
                 const float* __restrict__ Wn2, const float* __restrict__ bn2,
                 float* __restrict__ outH, int N)
{
  extern __shared__ char smem_raw[];
  NodeSmem& S = *reinterpret_cast<NodeSmem*>(smem_raw);
  float* sNM = S.sA;
  const int tid = threadIdx.x;
  const int n0  = blockIdx.x * TE;

  #pragma unroll 4
  for (int e = 0; e < TE; ++e) {
    int n = min(n0 + e, N - 1);
    S.sA[tid * PITCH + e]         = g_agg[(size_t)n * HID + tid];
    S.sA[(HID + tid) * PITCH + e] = __ldg(h + (size_t)n * HID + tid);
  }
  __syncthreads();

  ull acc[16];
  #pragma unroll
  for (int q = 0; q < 16; ++q) acc[q] = 0ull;
  gemv32p<2*HID>(Wn1, S.sA, tid, acc);
  {
    float b1 = __ldg(bn1 + tid);
    #pragma unroll
    for (int q = 0; q < 16; ++q) {
      float2 v = unpack2(acc[q]);
      acc[q] = pack2f(silu_f(v.x + b1), silu_f(v.y + b1));
    }
  }
  __syncthreads();
  #pragma unroll
  for (int q = 0; q < 16; ++q) {
    float2 v = unpack2(acc[q]);
    sNM[tid * PITCH + 2*q]     = v.x;
    sNM[tid * PITCH + 2*q + 1] = v.y;
  }
  __syncthreads();

  #pragma unroll
  for (int q = 0; q < 16; ++q) acc[q] = 0ull;
  gemv32p<HID>(Wn2, sNM, tid, acc);
  {
    float b2 = __ldg(bn2 + tid);
    #pragma unroll
    for (int q = 0; q < 16; ++q) {
      float2 v = unpack2(acc[q]);
      int eA = 2*q, eB = 2*q + 1;
      if (n0 + eA < N) {
        float hv = S.sA[(HID + tid) * PITCH + eA];
        outH[(size_t)(n0 + eA) * HID + tid] = hv + v.x + b2;
      }
      if (n0 + eB < N) {
        float hv = S.sA[(HID + tid) * PITCH + eB];
        outH[(size_t)(n0 + eB) * HID + tid] = hv + v.y + b2;
      }
    }
  }
}

__global__ void xout_kernel(const float* __restrict__ x, const int* __restrict__ mask,
                            float* __restrict__ outX, int N)
{
  int i = blockIdx.x * blockDim.x + threadIdx.x;
  if (i < N * 3) {
    int n = i / 3;
    outX[i] = x[i] + g_dx[i] * (float)mask[n];
  }
}

// ==================== launch ====================
extern "C" void kernel_launch(void* const* d_in, const int* in_sizes, int n_in,
                              void* d_out, int out_size) {
  const float *h, *x, *ea, *We1, *be1, *We2, *be2, *Wg, *bg;
  const float *Wn1, *bn1, *Wn2, *bn2, *Wx1, *bx1, *Wx2;
  const int *ei, *mask;

  const int E = in_sizes[2] / EF;
  const int N = in_sizes[0] / HID;
  const bool setup_order = (in_sizes[3] == 2 * E);

  if (setup_order) {
    h    = (const float*)d_in[0];  x    = (const float*)d_in[1];
    ea   = (const float*)d_in[2];  ei   = (const int*)  d_in[3];
    mask = (const int*)  d_in[4];
    We1  = (const float*)d_in[5];  be1  = (const float*)d_in[6];
    We2  = (const float*)d_in[7];  be2  = (const float*)d_in[8];
    Wg   = (const float*)d_in[9];  bg   = (const float*)d_in[10];
    Wn1  = (const float*)d_in[11]; bn1  = (const float*)d_in[12];
    Wn2  = (const float*)d_in[13]; bn2  = (const float*)d_in[14];
    Wx1  = (const float*)d_in[15]; bx1  = (const float*)d_in[16];
    Wx2  = (const float*)d_in[17];
  } else {
    h    = (const float*)d_in[0];  x    = (const float*)d_in[1];
    ea   = (const float*)d_in[2];
    We1  = (const float*)d_in[3];  be1  = (const float*)d_in[4];
    We2  = (const float*)d_in[5];  be2  = (const float*)d_in[6];
    Wg   = (const float*)d_in[7];  bg   = (const float*)d_in[8];
    Wn1  = (const float*)d_in[9];  bn1  = (const float*)d_in[10];
    Wn2  = (const float*)d_in[11]; bn2  = (const float*)d_in[12];
    Wx1  = (const float*)d_in[13]; bx1  = (const float*)d_in[14];
    Wx2  = (const float*)d_in[15];
    ei   = (const int*)  d_in[16]; mask = (const int*)  d_in[17];
  }

  float* outH = (float*)d_out;
  float* outX = outH + (size_t)N * HID;

  cudaFuncSetAttribute(edge_kernel, cudaFuncAttributeMaxDynamicSharedMemorySize, SMTOT);
  cudaFuncSetAttribute(node_kernel, cudaFuncAttributeMaxDynamicSharedMemorySize,
                       (int)sizeof(NodeSmem));

  // launches: zero(1) prep(2) wprep(3) edge(4) node(5) xout(6) -> ncu slot 4 = edge
  zero_kernel<<<(MAXN * HID + 255) / 256, 256>>>();

  prep_kernel<<<(N + TE - 1) / TE, 256>>>(h, We1, N);

  wprep_kernel<<<(128 * 136 + 255) / 256, 256>>>(We1, We2, Wx1);

  int eblocks = (E + MT - 1) / MT;
  edge_kernel<<<eblocks, 256, SMTOT>>>(x, ea, ei, be1, be2, Wg, bg, bx1, Wx2, E);

  int nblocks = (N + TE - 1) / TE;
  node_kernel<<<nblocks, 128, sizeof(NodeSmem)>>>(h, Wn1, bn1, Wn2, bn2, outH, N);

  xout_kernel<<<(N * 3 + 255) / 256, 256>>>(x, mask, outX, N);
}

// round 12
// speedup vs baseline: 9.3181x; 1.9784x over previous
#include <cuda_runtime.h>
#include <cuda_bf16.h>
#include <math.h>

#define HID   128
#define EF    4
#define NG    20
#define TE    32
#define PITCH 36
#define MAXN  20000
#define CUTOFF 10.0f
#define MT    128        // edges per block (M)

typedef unsigned long long ull;
typedef unsigned u32;

// ==================== device scratch ====================
__device__ float g_agg[MAXN * HID];
__device__ float g_dx [MAXN * 3];
__device__ float g_P  [MAXN * 256];                        // [P_dst | P_src]
__device__ __align__(16) __nv_bfloat16 g_W1T [128 * 40];   // Wrest^T [n][k] stride 40
__device__ __align__(16) __nv_bfloat16 g_We2T[128 * 136];  // We2^T  [n][k] stride 136
__device__ __align__(16) __nv_bfloat16 g_Wx1T[128 * 136];  // Wx1^T  [n][k] stride 136

// ==================== helpers ====================
__device__ __forceinline__ float silu_f(float v)    { return v / (1.f + __expf(-v)); }
__device__ __forceinline__ float sigmoid_f(float v) { return 1.f / (1.f + __expf(-v)); }
__device__ __forceinline__ u32 bf16pack(float lo, float hi) {
  u32 r;
  asm("cvt.rn.bf16x2.f32 %0, %1, %2;" : "=r"(r) : "f"(hi), "f"(lo));
  return r;
}
__device__ __forceinline__ void mma16816(float d[4], u32 a0, u32 a1, u32 a2, u32 a3,
                                         u32 b0, u32 b1) {
  asm volatile("mma.sync.aligned.m16n8k16.row.col.f32.bf16.bf16.f32 "
    "{%0,%1,%2,%3}, {%4,%5,%6,%7}, {%8,%9}, {%0,%1,%2,%3};"
    : "+f"(d[0]), "+f"(d[1]), "+f"(d[2]), "+f"(d[3])
    : "r"(a0), "r"(a1), "r"(a2), "r"(a3), "r"(b0), "r"(b1));
}

// ==================== smem layout (bytes) ====================
#define SDST   0
#define SSRC   512
#define SRELX  1024
#define SRELY  1536
#define SRELZ  2048
#define SRINV  2560
#define SRV    3072
#define SGATE  3584
#define SCOEF  4096
#define SREDG  4608     // 128*4 f32
#define SREDC  6656     // 128*4 f32
#define SBE1   8704
#define SBE2   9216
#define SBX1   9728
#define SWGV   10240
#define SWX2V  10752
#define SBGV   11264
#define SX     11392    // m1 bf16 tile, 128 rows x 272B stride  (34816)
#define SY     46208    // AREST (stride 80B) then m2 tile (stride 272B), aliased (34816)
#define SMTOT  81024

// ==================== zero ====================
__global__ void zero_kernel() {
  int i = blockIdx.x * blockDim.x + threadIdx.x;
  if (i < MAXN * HID) g_agg[i] = 0.f;
  if (i < MAXN * 3)   g_dx[i]  = 0.f;
}

// ==================== FFMA2 helpers (prep + node) ====================
__device__ __forceinline__ ull fma2(ull a, ull b, ull c) {
  ull d; asm("fma.rn.f32x2 %0, %1, %2, %3;" : "=l"(d) : "l"(a), "l"(b), "l"(c)); return d;
}
__device__ __forceinline__ ull pack_dup(float v) {
  ull d; unsigned uu = __float_as_uint(v);
  asm("mov.b64 %0, {%1, %1};" : "=l"(d) : "r"(uu)); return d;
}
__device__ __forceinline__ ull pack2f(float a, float b) {
  ull d; asm("mov.b64 %0, {%1, %2};" : "=l"(d) : "r"(__float_as_uint(a)), "r"(__float_as_uint(b))); return d;
}
__device__ __forceinline__ float2 unpack2(ull v) {
  unsigned lo, hi; asm("mov.b64 {%0, %1}, %2;" : "=r"(lo), "=r"(hi) : "l"(v));
  return make_float2(__uint_as_float(lo), __uint_as_float(hi));
}
template<int K>
__device__ __forceinline__ void gemv32p(const float* __restrict__ W,
                                        const float* __restrict__ sAT,
                                        int j, ull acc[16]) {
  #pragma unroll 4
  for (int k = 0; k < K; ++k) {
    ull w2 = pack_dup(__ldg(W + k * HID + j));
    const ulonglong2* a2 = reinterpret_cast<const ulonglong2*>(sAT + k * PITCH);
    #pragma unroll
    for (int q = 0; q < 8; ++q) {
      ulonglong2 v = a2[q];
      acc[2*q]   = fma2(v.x, w2, acc[2*q]);
      acc[2*q+1] = fma2(v.y, w2, acc[2*q+1]);
    }
  }
}

struct __align__(16) PrepSmem { alignas(16) float sH[HID * PITCH]; };

__global__ __launch_bounds__(256, 3)
void prep_kernel(const float* __restrict__ h, const float* __restrict__ We1, int N)
{
  __shared__ PrepSmem S;
  const int tid = threadIdx.x;
  const int n0  = blockIdx.x * TE;
  for (int idx = tid; idx < HID * TE; idx += 256) {
    int row = idx & 127, e = idx >> 7;
    int n = min(n0 + e, N - 1);
    S.sH[row * PITCH + e] = __ldg(h + (size_t)n * HID + row);
  }
  __syncthreads();
  const int sel = tid >> 7;
  const int j   = tid & 127;
  const float* Wbase = We1 + (size_t)sel * HID * HID;
  ull acc[16];
  #pragma unroll
  for (int q = 0; q < 16; ++q) acc[q] = 0ull;
  gemv32p<HID>(Wbase, S.sH, j, acc);
  #pragma unroll
  for (int q = 0; q < 16; ++q) {
    float2 v = unpack2(acc[q]);
    int eA = 2*q, eB = 2*q+1;
    if (n0 + eA < N) g_P[(size_t)(n0 + eA) * 256 + sel * 128 + j] = v.x;
    if (n0 + eB < N) g_P[(size_t)(n0 + eB) * 256 + sel * 128 + j] = v.y;
  }
}

__global__ void wprep_kernel(const float* __restrict__ We1,
                             const float* __restrict__ We2,
                             const float* __restrict__ Wx1)
{
  int i = blockIdx.x * blockDim.x + threadIdx.x;
  if (i < 128 * 40) {
    int n = i / 40, k = i % 40;
    float v = (k < NG + EF) ? We1[(256 + k) * HID + n] : 0.f;
    g_W1T[n * 40 + k] = __float2bfloat16(v);
  }
  if (i < 128 * 136) {
    int n = i / 136, k = i % 136;
    float v2 = (k < 128) ? We2[k * HID + n] : 0.f;
    float v3 = (k < 128) ? Wx1[k * HID + n] : 0.f;
    g_We2T[n * 136 + k] = __float2bfloat16(v2);
    g_Wx1T[n * 136 + k] = __float2bfloat16(v3);
  }
}

// ==================== edge kernel ====================
__global__ __launch_bounds__(256, 2)
void edge_kernel(const float* __restrict__ x,
                 const float* __restrict__ ea,  const int* __restrict__ ei,
                 const float* __restrict__ be1, const float* __restrict__ be2,
                 const float* __restrict__ Wg,  const float* __restrict__ bg,
                 const float* __restrict__ bx1, const float* __restrict__ Wx2,
                 int E)
{
  extern __shared__ char sm[];
  const int tid  = threadIdx.x;
  const int lane = tid & 31;
  const int w    = tid >> 5;
  const int g    = lane >> 2;        // groupID (row within 8)
  const int c    = lane & 3;         // thread-in-quad
  const int mr0  = (w >> 2) * 64;    // warp M origin (edges)
  const int nc0  = (w & 3) * 32;     // warp N origin (channels)
  const int e0   = blockIdx.x * MT;

  int*   sDst  = (int*)(sm + SDST);
  int*   sSrc  = (int*)(sm + SSRC);
  float* sRelX = (float*)(sm + SRELX);
  float* sRelY = (float*)(sm + SRELY);
  float* sRelZ = (float*)(sm + SRELZ);
  float* sRinv = (float*)(sm + SRINV);
  float* sR    = (float*)(sm + SRV);
  float* sG    = (float*)(sm + SGATE);
  float* sCoef = (float*)(sm + SCOEF);
  float* sRedG = (float*)(sm + SREDG);
  float* sRedC = (float*)(sm + SREDC);
  float* sBE1  = (float*)(sm + SBE1);
  float* sBE2  = (float*)(sm + SBE2);
  float* sBX1  = (float*)(sm + SBX1);
  float* sWG   = (float*)(sm + SWGV);
  float* sWX2  = (float*)(sm + SWX2V);

  if (tid < 128) {
    sBE1[tid] = be1[tid]; sBE2[tid] = be2[tid]; sBX1[tid] = bx1[tid];
    sWG[tid]  = Wg[tid];  sWX2[tid] = Wx2[tid];
  }
  if (tid == 0) *(float*)(sm + SBGV) = bg[0];
  if (tid < MT) {
    int eg = min(e0 + tid, E - 1);
    sSrc[tid] = ei[eg];
    sDst[tid] = ei[E + eg];
  }
  __syncthreads();   // sync1

  // geometry
  if (tid < MT) {
    int s = sSrc[tid], d0 = sDst[tid];
    float rx = x[d0*3+0] - x[s*3+0];
    float ry = x[d0*3+1] - x[s*3+1];
    float rz = x[d0*3+2] - x[s*3+2];
    float r  = sqrtf(rx*rx + ry*ry + rz*rz + 1e-8f);
    sRelX[tid] = rx; sRelY[tid] = ry; sRelZ[tid] = rz;
    sR[tid] = r; sRinv[tid] = 1.f / (r + 1.f);
  }

  // ---- stage-1 accumulators pre-loaded with P_dst + P_src (global gather,
  //      overlaps with the RBF staging below) ----
  float d[4][4][4];
  #pragma unroll
  for (int mi = 0; mi < 4; ++mi) {
    int row0 = mr0 + 16*mi + g, row1 = row0 + 8;
    const float* pd0 = g_P + (size_t)sDst[row0] * 256;
    const float* ps0 = g_P + (size_t)sSrc[row0] * 256 + 128;
    const float* pd1 = g_P + (size_t)sDst[row1] * 256;
    const float* ps1 = g_P + (size_t)sSrc[row1] * 256 + 128;
    #pragma unroll
    for (int ni = 0; ni < 4; ++ni) {
      int col = nc0 + 8*ni + 2*c;
      float2 a0 = __ldg((const float2*)(pd0 + col));
      float2 b0 = __ldg((const float2*)(ps0 + col));
      float2 a1 = __ldg((const float2*)(pd1 + col));
      float2 b1 = __ldg((const float2*)(ps1 + col));
      d[mi][ni][0] = a0.x + b0.x; d[mi][ni][1] = a0.y + b0.y;
      d[mi][ni][2] = a1.x + b1.x; d[mi][ni][3] = a1.y + b1.y;
    }
  }
  __syncthreads();   // sync2: sR ready for RBF

  // AREST bf16 into Y (stride 80B): cols 0..19 RBF, 20..23 ea, 24..31 zero
  {
    const float step  = CUTOFF / 19.f;
    const float coeff = -0.5f / (step * step);
    for (int i2 = tid; i2 < MT * NG; i2 += 256) {
      int e = i2 & 127, gi = i2 >> 7;
      float diff = sR[e] - (float)gi * step;
      *(__nv_bfloat16*)(sm + SY + e * 80 + gi * 2) =
          __float2bfloat16(__expf(coeff * diff * diff));
    }
    for (int i2 = tid; i2 < MT * EF; i2 += 256) {
      int e = i2 & 127, fi = i2 >> 7;
      int eg = min(e0 + e, E - 1);
      *(__nv_bfloat16*)(sm + SY + e * 80 + (NG + fi) * 2) =
          __float2bfloat16(ea[(size_t)eg * EF + fi]);
    }
    for (int i2 = tid; i2 < MT * 8; i2 += 256) {
      int e = i2 & 127, k = 24 + (i2 >> 7);
      *(__nv_bfloat16*)(sm + SY + e * 80 + k * 2) = __float2bfloat16(0.f);
    }
  }
  __syncthreads();   // sync3: AREST staged

  // ---------------- stage 1: D += rest @ WrestT (K=32) ----------------
  #pragma unroll
  for (int kc = 0; kc < 2; ++kc) {
    const int k0 = kc * 16;
    u32 b[4][2];
    #pragma unroll
    for (int ni = 0; ni < 4; ++ni) {
      const __nv_bfloat16* wp = g_W1T + (nc0 + 8*ni + g) * 40 + (k0 + 2*c);
      b[ni][0] = __ldg((const u32*)wp);
      b[ni][1] = __ldg((const u32*)(wp + 8));
    }
    #pragma unroll
    for (int mi = 0; mi < 4; ++mi) {
      const char* ap = sm + SY + (mr0 + 16*mi + g) * 80 + (k0 + 2*c) * 2;
      u32 a0 = *(const u32*)ap;
      u32 a1 = *(const u32*)(ap + 8 * 80);
      u32 a2 = *(const u32*)(ap + 16);
      u32 a3 = *(const u32*)(ap + 8 * 80 + 16);
      #pragma unroll
      for (int ni = 0; ni < 4; ++ni)
        mma16816(d[mi][ni], a0, a1, a2, a3, b[ni][0], b[ni][1]);
    }
  }

  // epilogue 1: m1 = silu(D + be1) -> X (no sync needed: X untouched so far)
  #pragma unroll
  for (int mi = 0; mi < 4; ++mi)
    #pragma unroll
    for (int ni = 0; ni < 4; ++ni) {
      int row = mr0 + 16*mi + g, col = nc0 + 8*ni + 2*c;
      float b0 = sBE1[col], b1 = sBE1[col + 1];
      float v0 = silu_f(d[mi][ni][0] + b0), v1 = silu_f(d[mi][ni][1] + b1);
      float v2 = silu_f(d[mi][ni][2] + b0), v3 = silu_f(d[mi][ni][3] + b1);
      *(u32*)(sm + SX + row * 272 + col * 2)       = bf16pack(v0, v1);
      *(u32*)(sm + SX + (row + 8) * 272 + col * 2) = bf16pack(v2, v3);
    }
  __syncthreads();   // sync4: X(m1) visible; Y reads all done

  // ---------------- stage 2: D = m1 @ We2T ----------------
  #pragma unroll
  for (int mi = 0; mi < 4; ++mi)
    #pragma unroll
    for (int ni = 0; ni < 4; ++ni) {
      d[mi][ni][0] = 0.f; d[mi][ni][1] = 0.f; d[mi][ni][2] = 0.f; d[mi][ni][3] = 0.f;
    }
  #pragma unroll
  for (int kc = 0; kc < 8; ++kc) {
    const int k0 = kc * 16;
    u32 b[4][2];
    #pragma unroll
    for (int ni = 0; ni < 4; ++ni) {
      const __nv_bfloat16* wp = g_We2T + (nc0 + 8*ni + g) * 136 + (k0 + 2*c);
      b[ni][0] = __ldg((const u32*)wp);
      b[ni][1] = __ldg((const u32*)(wp + 8));
    }
    #pragma unroll
    for (int mi = 0; mi < 4; ++mi) {
      const char* ap = sm + SX + (mr0 + 16*mi + g) * 272 + (k0 + 2*c) * 2;
      u32 a0 = *(const u32*)ap;
      u32 a1 = *(const u32*)(ap + 8 * 272);
      u32 a2 = *(const u32*)(ap + 16);
      u32 a3 = *(const u32*)(ap + 8 * 272 + 16);
      #pragma unroll
      for (int ni = 0; ni < 4; ++ni)
        mma16816(d[mi][ni], a0, a1, a2, a3, b[ni][0], b[ni][1]);
    }
  }

  // epilogue 2: m2 = silu(D + be2) -> Y (AREST dead); gate partials
  {
    float gp[4][2];
    #pragma unroll
    for (int mi = 0; mi < 4; ++mi) { gp[mi][0] = 0.f; gp[mi][1] = 0.f; }
    #pragma unroll
    for (int mi = 0; mi < 4; ++mi)
      #pragma unroll
      for (int ni = 0; ni < 4; ++ni) {
        int row = mr0 + 16*mi + g, col = nc0 + 8*ni + 2*c;
        float b0 = sBE2[col], b1 = sBE2[col + 1];
        float w0 = sWG[col],  w1 = sWG[col + 1];
        float v0 = silu_f(d[mi][ni][0] + b0), v1 = silu_f(d[mi][ni][1] + b1);
        float v2 = silu_f(d[mi][ni][2] + b0), v3 = silu_f(d[mi][ni][3] + b1);
        gp[mi][0] = fmaf(v0, w0, fmaf(v1, w1, gp[mi][0]));
        gp[mi][1] = fmaf(v2, w0, fmaf(v3, w1, gp[mi][1]));
        *(u32*)(sm + SY + row * 272 + col * 2)       = bf16pack(v0, v1);
        *(u32*)(sm + SY + (row + 8) * 272 + col * 2) = bf16pack(v2, v3);
      }
    #pragma unroll
    for (int mi = 0; mi < 4; ++mi)
      #pragma unroll
      for (int rh = 0; rh < 2; ++rh) {
        float p = gp[mi][rh];
        p += __shfl_xor_sync(0xffffffffu, p, 1);
        p += __shfl_xor_sync(0xffffffffu, p, 2);
        if (c == 0) sRedG[(mr0 + 16*mi + 8*rh + g) * 4 + (w & 3)] = p;
      }
  }
  __syncthreads();   // sync5: Y(m2) visible

  // ---------------- stage 3: D = m2 @ Wx1T ----------------
  #pragma unroll
  for (int mi = 0; mi < 4; ++mi)
    #pragma unroll
    for (int ni = 0; ni < 4; ++ni) {
      d[mi][ni][0] = 0.f; d[mi][ni][1] = 0.f; d[mi][ni][2] = 0.f; d[mi][ni][3] = 0.f;
    }
  #pragma unroll
  for (int kc = 0; kc < 8; ++kc) {
    const int k0 = kc * 16;
    u32 b[4][2];
    #pragma unroll
    for (int ni = 0; ni < 4; ++ni) {
      const __nv_bfloat16* wp = g_Wx1T + (nc0 + 8*ni + g) * 136 + (k0 + 2*c);
      b[ni][0] = __ldg((const u32*)wp);
      b[ni][1] = __ldg((const u32*)(wp + 8));
    }
    #pragma unroll
    for (int mi = 0; mi < 4; ++mi) {
      const char* ap = sm + SY + (mr0 + 16*mi + g) * 272 + (k0 + 2*c) * 2;
      u32 a0 = *(const u32*)ap;
      u32 a1 = *(const u32*)(ap + 8 * 272);
      u32 a2 = *(const u32*)(ap + 16);
      u32 a3 = *(const u32*)(ap + 8 * 272 + 16);
      #pragma unroll
      for (int ni = 0; ni < 4; ++ni)
        mma16816(d[mi][ni], a0, a1, a2, a3, b[ni][0], b[ni][1]);
    }
  }
  // epilogue 3: coef partials = silu(D + bx1) . Wx2
  {
    float cp[4][2];
    #pragma unroll
    for (int mi = 0; mi < 4; ++mi) { cp[mi][0] = 0.f; cp[mi][1] = 0.f; }
    #pragma unroll
    for (int mi = 0; mi < 4; ++mi)
      #pragma unroll
      for (int ni = 0; ni < 4; ++ni) {
        int col = nc0 + 8*ni + 2*c;
        float b0 = sBX1[col], b1 = sBX1[col + 1];
        float w0 = sWX2[col], w1 = sWX2[col + 1];
        float v0 = silu_f(d[mi][ni][0] + b0), v1 = silu_f(d[mi][ni][1] + b1);
        float v2 = silu_f(d[mi][ni][2] + b0), v3 = silu_f(d[mi][ni][3] + b1);
        cp[mi][0] = fmaf(v0, w0, fmaf(v1, w1, cp[mi][0]));
        cp[mi][1] = fmaf(v2, w0, fmaf(v3, w1, cp[mi][1]));
      }
    #pragma unroll
    for (int mi = 0; mi < 4; ++mi)
      #pragma unroll
      for (int rh = 0; rh < 2; ++rh) {
        float p = cp[mi][rh];
        p += __shfl_xor_sync(0xffffffffu, p, 1);
        p += __shfl_xor_sync(0xffffffffu, p, 2);
        if (c == 0) sRedC[(mr0 + 16*mi + 8*rh + g) * 4 + (w & 3)] = p;
      }
  }
  __syncthreads();   // sync6

  // finalize gate + coef
  if (tid < MT) {
    float sg = sRedG[tid*4+0] + sRedG[tid*4+1] + sRedG[tid*4+2] + sRedG[tid*4+3]
             + *(float*)(sm + SBGV);
    sG[tid] = sigmoid_f(sg);
    float sc = sRedC[tid*4+0] + sRedC[tid*4+1] + sRedC[tid*4+2] + sRedC[tid*4+3];
    sCoef[tid] = tanhf(sc);
  }
  __syncthreads();   // sync7

  // scatter: agg += m2 * g  (channel-parallel, coalesced atomics)
  {
    const int j = tid & 127, half = tid >> 7;
    #pragma unroll 4
    for (int e = half * 64; e < half * 64 + 64; ++e) {
      if (e0 + e < E) {
        float m2v = __bfloat162float(*(const __nv_bfloat16*)(sm + SY + e * 272 + j * 2));
        atomicAdd(&g_agg[(size_t)sDst[e] * HID + j], m2v * sG[e]);
      }
    }
  }
  if (tid < MT && (e0 + tid < E)) {
    int dd = sDst[tid];
    float cc = sCoef[tid] * sRinv[tid];
    atomicAdd(&g_dx[dd*3+0], sRelX[tid] * cc);
    atomicAdd(&g_dx[dd*3+1], sRelY[tid] * cc);
    atomicAdd(&g_dx[dd*3+2], sRelZ[tid] * cc);
  }
}

// ==================== node kernel (FFMA2) ====================
struct __align__(16) NodeSmem { alignas(16) float sA[2*HID * PITCH]; };

__global__ __launch_bounds__(128, 4)
void node_kernel(const float* __restrict__ h,
                 const float* __restrict__ Wn1, const float* __restrict__ bn1,
                 const float* __restrict__ Wn2, const float* __restrict__ bn2,
                 float* __restrict__ outH, int N)
{
  extern __shared__ char smem_raw[];
  NodeSmem& S = *reinterpret_cast<NodeSmem*>(smem_raw);
  float* sNM = S.sA;
  const int tid = threadIdx.x;
  const int n0  = blockIdx.x * TE;

  #pragma unroll 4
  for (int e = 0; e < TE; ++e) {
    int n = min(n0 + e, N - 1);
    S.sA[tid * PITCH + e]         = g_agg[(size_t)n * HID + tid];
    S.sA[(HID + tid) * PITCH + e] = __ldg(h + (size_t)n * HID + tid);
  }
  __syncthreads();

  ull acc[16];
  #pragma unroll
  for (int q = 0; q < 16; ++q) acc[q] = 0ull;
  gemv32p<2*HID>(Wn1, S.sA, tid, acc);
  {
    float b1 = __ldg(bn1 + tid);
    #pragma unroll
    for (int q = 0; q < 16; ++q) {
      float2 v = unpack2(acc[q]);
      acc[q] = pack2f(silu_f(v.x + b1), silu_f(v.y + b1));
    }
  }
  __syncthreads();
  #pragma unroll
  for (int q = 0; q < 16; ++q) {
    float2 v = unpack2(acc[q]);
    sNM[tid * PITCH + 2*q]     = v.x;
    sNM[tid * PITCH + 2*q + 1] = v.y;
  }
  __syncthreads();

  #pragma unroll
  for (int q = 0; q < 16; ++q) acc[q] = 0ull;
  gemv32p<HID>(Wn2, sNM, tid, acc);
  {
    float b2 = __ldg(bn2 + tid);
    #pragma unroll
    for (int q = 0; q < 16; ++q) {
      float2 v = unpack2(acc[q]);
      int eA = 2*q, eB = 2*q + 1;
      if (n0 + eA < N) {
        float hv = S.sA[(HID + tid) * PITCH + eA];
        outH[(size_t)(n0 + eA) * HID + tid] = hv + v.x + b2;
      }
      if (n0 + eB < N) {
        float hv = S.sA[(HID + tid) * PITCH + eB];
        outH[(size_t)(n0 + eB) * HID + tid] = hv + v.y + b2;
      }
    }
  }
}

__global__ void xout_kernel(const float* __restrict__ x, const int* __restrict__ mask,
                            float* __restrict__ outX, int N)
{
  int i = blockIdx.x * blockDim.x + threadIdx.x;
  if (i < N * 3) {
    int n = i / 3;
    outX[i] = x[i] + g_dx[i] * (float)mask[n];
  }
}

// ==================== launch ====================
extern "C" void kernel_launch(void* const* d_in, const int* in_sizes, int n_in,
                              void* d_out, int out_size) {
  const float *h, *x, *ea, *We1, *be1, *We2, *be2, *Wg, *bg;
  const float *Wn1, *bn1, *Wn2, *bn2, *Wx1, *bx1, *Wx2;
  const int *ei, *mask;

  const int E = in_sizes[2] / EF;
  const int N = in_sizes[0] / HID;
  const bool setup_order = (in_sizes[3] == 2 * E);

  if (setup_order) {
    h    = (const float*)d_in[0];  x    = (const float*)d_in[1];
    ea   = (const float*)d_in[2];  ei   = (const int*)  d_in[3];
    mask = (const int*)  d_in[4];
    We1  = (const float*)d_in[5];  be1  = (const float*)d_in[6];
    We2  = (const float*)d_in[7];  be2  = (const float*)d_in[8];
    Wg   = (const float*)d_in[9];  bg   = (const float*)d_in[10];
    Wn1  = (const float*)d_in[11]; bn1  = (const float*)d_in[12];
    Wn2  = (const float*)d_in[13]; bn2  = (const float*)d_in[14];
    Wx1  = (const float*)d_in[15]; bx1  = (const float*)d_in[16];
    Wx2  = (const float*)d_in[17];
  } else {
    h    = (const float*)d_in[0];  x    = (const float*)d_in[1];
    ea   = (const float*)d_in[2];
    We1  = (const float*)d_in[3];  be1  = (const float*)d_in[4];
    We2  = (const float*)d_in[5];  be2  = (const float*)d_in[6];
    Wg   = (const float*)d_in[7];  bg   = (const float*)d_in[8];
    Wn1  = (const float*)d_in[9];  bn1  = (const float*)d_in[10];
    Wn2  = (const float*)d_in[11]; bn2  = (const float*)d_in[12];
    Wx1  = (const float*)d_in[13]; bx1  = (const float*)d_in[14];
    Wx2  = (const float*)d_in[15];
    ei   = (const int*)  d_in[16]; mask = (const int*)  d_in[17];
  }

  float* outH = (float*)d_out;
  float* outX = outH + (size_t)N * HID;

  cudaFuncSetAttribute(edge_kernel, cudaFuncAttributeMaxDynamicSharedMemorySize, SMTOT);
  cudaFuncSetAttribute(node_kernel, cudaFuncAttributeMaxDynamicSharedMemorySize,
                       (int)sizeof(NodeSmem));

  // launches: zero(1) prep(2) wprep(3) edge(4) node(5) xout(6) -> ncu slot 4 = edge
  zero_kernel<<<(MAXN * HID + 255) / 256, 256>>>();

  prep_kernel<<<(N + TE - 1) / TE, 256>>>(h, We1, N);

  wprep_kernel<<<(128 * 136 + 255) / 256, 256>>>(We1, We2, Wx1);

  int eblocks = (E + MT - 1) / MT;
  edge_kernel<<<eblocks, 256, SMTOT>>>(x, ea, ei, be1, be2, Wg, bg, bx1, Wx2, E);

  int nblocks = (N + TE - 1) / TE;
  node_kernel<<<nblocks, 128, sizeof(NodeSmem)>>>(h, Wn1, bn1, Wn2, bn2, outH, N);

  xout_kernel<<<(N * 3 + 255) / 256, 256>>>(x, mask, outX, N);
}

// round 15
// speedup vs baseline: 10.4921x; 1.1260x over previous
#include <cuda_runtime.h>
#include <cuda_bf16.h>
#include <math.h>

#define HID   128
#define EF    4
#define NG    20
#define TE    32
#define PITCH 36
#define MAXN  20000
#define CUTOFF 10.0f
#define MT    128        // edges per block (M)

typedef unsigned long long ull;
typedef unsigned u32;

// ==================== device scratch ====================
__device__ float g_agg[MAXN * HID];
__device__ float g_dx [MAXN * 3];
__device__ float g_P  [MAXN * 256];                        // [P_dst | P_src]
__device__ __align__(16) __nv_bfloat16 g_W1T  [128 * 40];  // Wrest^T [n][k] stride 40
__device__ __align__(16) __nv_bfloat16 g_We2T [128 * 136]; // We2^T   stride 136
__device__ __align__(16) __nv_bfloat16 g_Wx1T [128 * 136]; // Wx1^T
__device__ __align__(16) __nv_bfloat16 g_Wn1aT[128 * 136]; // Wn1 rows 0..127 ^T
__device__ __align__(16) __nv_bfloat16 g_Wn1bT[128 * 136]; // Wn1 rows 128..255 ^T
__device__ __align__(16) __nv_bfloat16 g_Wn2T [128 * 136]; // Wn2^T

// ==================== helpers ====================
__device__ __forceinline__ float silu_f(float v)    { return v / (1.f + __expf(-v)); }
__device__ __forceinline__ float sigmoid_f(float v) { return 1.f / (1.f + __expf(-v)); }
__device__ __forceinline__ u32 bf16pack(float lo, float hi) {
  u32 r;
  asm("cvt.rn.bf16x2.f32 %0, %1, %2;" : "=r"(r) : "f"(hi), "f"(lo));
  return r;
}
__device__ __forceinline__ unsigned smem_u32(const void* p) {
  unsigned a;
  asm("{ .reg .u64 t; cvta.to.shared.u64 t, %1; cvt.u32.u64 %0, t; }" : "=r"(a) : "l"(p));
  return a;
}
__device__ __forceinline__ void mma16816(float d[4], u32 a0, u32 a1, u32 a2, u32 a3,
                                         u32 b0, u32 b1) {
  asm volatile("mma.sync.aligned.m16n8k16.row.col.f32.bf16.bf16.f32 "
    "{%0,%1,%2,%3}, {%4,%5,%6,%7}, {%8,%9}, {%0,%1,%2,%3};"
    : "+f"(d[0]), "+f"(d[1]), "+f"(d[2]), "+f"(d[3])
    : "r"(a0), "r"(a1), "r"(a2), "r"(a3), "r"(b0), "r"(b1));
}
__device__ __forceinline__ void ldmA(u32& a0, u32& a1, u32& a2, u32& a3, unsigned addr) {
  asm volatile("ldmatrix.sync.aligned.m8n8.x4.shared.b16 {%0,%1,%2,%3}, [%4];"
    : "=r"(a0), "=r"(a1), "=r"(a2), "=r"(a3) : "r"(addr));
}

// ==================== edge smem layout (bytes) ====================
#define SDST   0
#define SSRC   512
#define SRELX  1024
#define SRELY  1536
#define SRELZ  2048
#define SRINV  2560
#define SRV    3072
#define SGATE  3584
#define SCOEF  4096
#define SREDG  4608     // 128*4 f32
#define SREDC  6656     // 128*4 f32
#define SBE1   8704
#define SBE2   9216
#define SBX1   9728
#define SWGV   10240
#define SWX2V  10752
#define SBGV   11264
#define SAREST 11392    // 128 x 40 bf16 (stride 80B)   10240
#define SX     21632    // m1 then m2 tile, 128 x 272B  34816
#define SMTOT  56448

// ==================== zero ====================
__global__ void zero_kernel() {
  int i = blockIdx.x * blockDim.x + threadIdx.x;
  if (i < MAXN * HID) g_agg[i] = 0.f;
  if (i < MAXN * 3)   g_dx[i]  = 0.f;
}

// ==================== FFMA2 helpers (prep) ====================
__device__ __forceinline__ ull fma2(ull a, ull b, ull c) {
  ull d; asm("fma.rn.f32x2 %0, %1, %2, %3;" : "=l"(d) : "l"(a), "l"(b), "l"(c)); return d;
}
__device__ __forceinline__ ull pack_dup(float v) {
  ull d; unsigned uu = __float_as_uint(v);
  asm("mov.b64 %0, {%1, %1};" : "=l"(d) : "r"(uu)); return d;
}
__device__ __forceinline__ float2 unpack2(ull v) {
  unsigned lo, hi; asm("mov.b64 {%0, %1}, %2;" : "=r"(lo), "=r"(hi) : "l"(v));
  return make_float2(__uint_as_float(lo), __uint_as_float(hi));
}
template<int K>
__device__ __forceinline__ void gemv32p(const float* __restrict__ W,
                                        const float* __restrict__ sAT,
                                        int j, ull acc[16]) {
  #pragma unroll 4
  for (int k = 0; k < K; ++k) {
    ull w2 = pack_dup(__ldg(W + k * HID + j));
    const ulonglong2* a2 = reinterpret_cast<const ulonglong2*>(sAT + k * PITCH);
    #pragma unroll
    for (int q = 0; q < 8; ++q) {
      ulonglong2 v = a2[q];
      acc[2*q]   = fma2(v.x, w2, acc[2*q]);
      acc[2*q+1] = fma2(v.y, w2, acc[2*q+1]);
    }
  }
}

struct __align__(16) PrepSmem { alignas(16) float sH[HID * PITCH]; };

__global__ __launch_bounds__(256, 3)
void prep_kernel(const float* __restrict__ h, const float* __restrict__ We1, int N)
{
  __shared__ PrepSmem S;
  const int tid = threadIdx.x;
  const int n0  = blockIdx.x * TE;
  for (int idx = tid; idx < HID * TE; idx += 256) {
    int row = idx & 127, e = idx >> 7;
    int n = min(n0 + e, N - 1);
    S.sH[row * PITCH + e] = __ldg(h + (size_t)n * HID + row);
  }
  __syncthreads();
  const int sel = tid >> 7;
  const int j   = tid & 127;
  const float* Wbase = We1 + (size_t)sel * HID * HID;
  ull acc[16];
  #pragma unroll
  for (int q = 0; q < 16; ++q) acc[q] = 0ull;
  gemv32p<HID>(Wbase, S.sH, j, acc);
  #pragma unroll
  for (int q = 0; q < 16; ++q) {
    float2 v = unpack2(acc[q]);
    int eA = 2*q, eB = 2*q+1;
    if (n0 + eA < N) g_P[(size_t)(n0 + eA) * 256 + sel * 128 + j] = v.x;
    if (n0 + eB < N) g_P[(size_t)(n0 + eB) * 256 + sel * 128 + j] = v.y;
  }
}

__global__ void wprep_kernel(const float* __restrict__ We1,
                             const float* __restrict__ We2,
                             const float* __restrict__ Wx1,
                             const float* __restrict__ Wn1,
                             const float* __restrict__ Wn2)
{
  int i = blockIdx.x * blockDim.x + threadIdx.x;
  if (i < 128 * 40) {
    int n = i / 40, k = i % 40;
    float v = (k < NG + EF) ? We1[(256 + k) * HID + n] : 0.f;
    g_W1T[n * 40 + k] = __float2bfloat16(v);
  }
  if (i < 128 * 136) {
    int n = i / 136, k = i % 136;
    bool ok = (k < 128);
    g_We2T [n * 136 + k] = __float2bfloat16(ok ? We2[k * HID + n] : 0.f);
    g_Wx1T [n * 136 + k] = __float2bfloat16(ok ? Wx1[k * HID + n] : 0.f);
    g_Wn1aT[n * 136 + k] = __float2bfloat16(ok ? Wn1[k * HID + n] : 0.f);
    g_Wn1bT[n * 136 + k] = __float2bfloat16(ok ? Wn1[(128 + k) * HID + n] : 0.f);
    g_Wn2T [n * 136 + k] = __float2bfloat16(ok ? Wn2[k * HID + n] : 0.f);
  }
}

// ==================== edge kernel ====================
__global__ __launch_bounds__(256, 2)
void edge_kernel(const float* __restrict__ x,
                 const float* __restrict__ ea,  const int* __restrict__ ei,
                 const float* __restrict__ be1, const float* __restrict__ be2,
                 const float* __restrict__ Wg,  const float* __restrict__ bg,
                 const float* __restrict__ bx1, const float* __restrict__ Wx2,
                 int E)
{
  extern __shared__ char sm[];
  const unsigned sbu = smem_u32(sm);
  const int tid  = threadIdx.x;
  const int lane = tid & 31;
  const int w    = tid >> 5;
  const int g    = lane >> 2;
  const int c    = lane & 3;
  const int mr0  = (w >> 2) * 64;
  const int nc0  = (w & 3) * 32;
  const int e0   = blockIdx.x * MT;
  const int rsel = lane & 15;          // ldmatrix row-in-16
  const int ksh  = (lane >> 4) << 3;   // ldmatrix k half-shift

  int*   sDst  = (int*)(sm + SDST);
  int*   sSrc  = (int*)(sm + SSRC);
  float* sRelX = (float*)(sm + SRELX);
  float* sRelY = (float*)(sm + SRELY);
  float* sRelZ = (float*)(sm + SRELZ);
  float* sRinv = (float*)(sm + SRINV);
  float* sR    = (float*)(sm + SRV);
  float* sG    = (float*)(sm + SGATE);
  float* sCoef = (float*)(sm + SCOEF);
  float* sRedG = (float*)(sm + SREDG);
  float* sRedC = (float*)(sm + SREDC);
  float* sBE1  = (float*)(sm + SBE1);
  float* sBE2  = (float*)(sm + SBE2);
  float* sBX1  = (float*)(sm + SBX1);
  float* sWG   = (float*)(sm + SWGV);
  float* sWX2  = (float*)(sm + SWX2V);

  if (tid < 128) {
    sBE1[tid] = be1[tid]; sBE2[tid] = be2[tid]; sBX1[tid] = bx1[tid];
    sWG[tid]  = Wg[tid];  sWX2[tid] = Wx2[tid];
  }
  if (tid == 0) *(float*)(sm + SBGV) = bg[0];
  if (tid < MT) {
    int eg = min(e0 + tid, E - 1);
    sSrc[tid] = ei[eg];
    sDst[tid] = ei[E + eg];
  }
  __syncthreads();   // sync1

  if (tid < MT) {
    int s = sSrc[tid], d0 = sDst[tid];
    float rx = x[d0*3+0] - x[s*3+0];
    float ry = x[d0*3+1] - x[s*3+1];
    float rz = x[d0*3+2] - x[s*3+2];
    float r  = sqrtf(rx*rx + ry*ry + rz*rz + 1e-8f);
    sRelX[tid] = rx; sRelY[tid] = ry; sRelZ[tid] = rz;
    sR[tid] = r; sRinv[tid] = 1.f / (r + 1.f);
  }

  // stage-1 accumulators pre-loaded with P_dst + P_src
  float d[4][4][4];
  #pragma unroll
  for (int mi = 0; mi < 4; ++mi) {
    int row0 = mr0 + 16*mi + g, row1 = row0 + 8;
    const float* pd0 = g_P + (size_t)sDst[row0] * 256;
    const float* ps0 = g_P + (size_t)sSrc[row0] * 256 + 128;
    const float* pd1 = g_P + (size_t)sDst[row1] * 256;
    const float* ps1 = g_P + (size_t)sSrc[row1] * 256 + 128;
    #pragma unroll
    for (int ni = 0; ni < 4; ++ni) {
      int col = nc0 + 8*ni + 2*c;
      float2 a0 = __ldg((const float2*)(pd0 + col));
      float2 b0 = __ldg((const float2*)(ps0 + col));
      float2 a1 = __ldg((const float2*)(pd1 + col));
      float2 b1 = __ldg((const float2*)(ps1 + col));
      d[mi][ni][0] = a0.x + b0.x; d[mi][ni][1] = a0.y + b0.y;
      d[mi][ni][2] = a1.x + b1.x; d[mi][ni][3] = a1.y + b1.y;
    }
  }
  __syncthreads();   // sync2: sR ready

  // AREST bf16 (stride 80B): cols 0..19 RBF, 20..23 ea, 24..31 zero
  {
    const float step  = CUTOFF / 19.f;
    const float coeff = -0.5f / (step * step);
    for (int i2 = tid; i2 < MT * NG; i2 += 256) {
      int e = i2 & 127, gi = i2 >> 7;
      float diff = sR[e] - (float)gi * step;
      *(__nv_bfloat16*)(sm + SAREST + e * 80 + gi * 2) =
          __float2bfloat16(__expf(coeff * diff * diff));
    }
    for (int i2 = tid; i2 < MT * EF; i2 += 256) {
      int e = i2 & 127, fi = i2 >> 7;
      int eg = min(e0 + e, E - 1);
      *(__nv_bfloat16*)(sm + SAREST + e * 80 + (NG + fi) * 2) =
          __float2bfloat16(ea[(size_t)eg * EF + fi]);
    }
    for (int i2 = tid; i2 < MT * 8; i2 += 256) {
      int e = i2 & 127, k = 24 + (i2 >> 7);
      *(__nv_bfloat16*)(sm + SAREST + e * 80 + k * 2) = __float2bfloat16(0.f);
    }
  }
  __syncthreads();   // sync3

  // ---------------- stage 1: D += rest @ WrestT (K=32) ----------------
  #pragma unroll
  for (int kc = 0; kc < 2; ++kc) {
    const int k0 = kc * 16;
    u32 b[4][2];
    #pragma unroll
    for (int ni = 0; ni < 4; ++ni) {
      const __nv_bfloat16* wp = g_W1T + (nc0 + 8*ni + g) * 40 + (k0 + 2*c);
      b[ni][0] = __ldg((const u32*)wp);
      b[ni][1] = __ldg((const u32*)(wp + 8));
    }
    #pragma unroll
    for (int mi = 0; mi < 4; ++mi) {
      unsigned aaddr = sbu + SAREST + (mr0 + 16*mi + rsel) * 80 + (k0 + ksh) * 2;
      u32 a0, a1, a2, a3;
      ldmA(a0, a1, a2, a3, aaddr);
      #pragma unroll
      for (int ni = 0; ni < 4; ++ni)
        mma16816(d[mi][ni], a0, a1, a2, a3, b[ni][0], b[ni][1]);
    }
  }

  // epilogue 1: m1 = silu(D + be1) -> X (X untouched so far, no pre-sync)
  #pragma unroll
  for (int mi = 0; mi < 4; ++mi)
    #pragma unroll
    for (int ni = 0; ni < 4; ++ni) {
      int row = mr0 + 16*mi + g, col = nc0 + 8*ni + 2*c;
      float b0 = sBE1[col], b1 = sBE1[col + 1];
      float v0 = silu_f(d[mi][ni][0] + b0), v1 = silu_f(d[mi][ni][1] + b1);
      float v2 = silu_f(d[mi][ni][2] + b0), v3 = silu_f(d[mi][ni][3] + b1);
      *(u32*)(sm + SX + row * 272 + col * 2)       = bf16pack(v0, v1);
      *(u32*)(sm + SX + (row + 8) * 272 + col * 2) = bf16pack(v2, v3);
    }
  __syncthreads();   // sync4: X(m1) visible

  // ---------------- stage 2: D = m1 @ We2T ----------------
  #pragma unroll
  for (int mi = 0; mi < 4; ++mi)
    #pragma unroll
    for (int ni = 0; ni < 4; ++ni) {
      d[mi][ni][0] = 0.f; d[mi][ni][1] = 0.f; d[mi][ni][2] = 0.f; d[mi][ni][3] = 0.f;
    }
  #pragma unroll
  for (int kc = 0; kc < 8; ++kc) {
    const int k0 = kc * 16;
    u32 b[4][2];
    #pragma unroll
    for (int ni = 0; ni < 4; ++ni) {
      const __nv_bfloat16* wp = g_We2T + (nc0 + 8*ni + g) * 136 + (k0 + 2*c);
      b[ni][0] = __ldg((const u32*)wp);
      b[ni][1] = __ldg((const u32*)(wp + 8));
    }
    #pragma unroll
    for (int mi = 0; mi < 4; ++mi) {
      unsigned aaddr = sbu + SX + (mr0 + 16*mi + rsel) * 272 + (k0 + ksh) * 2;
      u32 a0, a1, a2, a3;
      ldmA(a0, a1, a2, a3, aaddr);
      #pragma unroll
      for (int ni = 0; ni < 4; ++ni)
        mma16816(d[mi][ni], a0, a1, a2, a3, b[ni][0], b[ni][1]);
    }
  }
  __syncthreads();   // sync5a: all MMA2 reads of X done

  // epilogue 2: m2 = silu(D + be2) -> X (overwrite m1); gate partials
  {
    float gp[4][2];
    #pragma unroll
    for (int mi = 0; mi < 4; ++mi) { gp[mi][0] = 0.f; gp[mi][1] = 0.f; }
    #pragma unroll
    for (int mi = 0; mi < 4; ++mi)
      #pragma unroll
      for (int ni = 0; ni < 4; ++ni) {
        int row = mr0 + 16*mi + g, col = nc0 + 8*ni + 2*c;
        float b0 = sBE2[col], b1 = sBE2[col + 1];
        float w0 = sWG[col],  w1 = sWG[col + 1];
        float v0 = silu_f(d[mi][ni][0] + b0), v1 = silu_f(d[mi][ni][1] + b1);
        float v2 = silu_f(d[mi][ni][2] + b0), v3 = silu_f(d[mi][ni][3] + b1);
        gp[mi][0] = fmaf(v0, w0, fmaf(v1, w1, gp[mi][0]));
        gp[mi][1] = fmaf(v2, w0, fmaf(v3, w1, gp[mi][1]));
        *(u32*)(sm + SX + row * 272 + col * 2)       = bf16pack(v0, v1);
        *(u32*)(sm + SX + (row + 8) * 272 + col * 2) = bf16pack(v2, v3);
      }
    #pragma unroll
    for (int mi = 0; mi < 4; ++mi)
      #pragma unroll
      for (int rh = 0; rh < 2; ++rh) {
        float p = gp[mi][rh];
        p += __shfl_xor_sync(0xffffffffu, p, 1);
        p += __shfl_xor_sync(0xffffffffu, p, 2);
        if (c == 0) sRedG[(mr0 + 16*mi + 8*rh + g) * 4 + (w & 3)] = p;
      }
  }
  __syncthreads();   // sync5b: X(m2) visible

  // ---------------- stage 3: D = m2 @ Wx1T ----------------
  #pragma unroll
  for (int mi = 0; mi < 4; ++mi)
    #pragma unroll
    for (int ni = 0; ni < 4; ++ni) {
      d[mi][ni][0] = 0.f; d[mi][ni][1] = 0.f; d[mi][ni][2] = 0.f; d[mi][ni][3] = 0.f;
    }
  #pragma unroll
  for (int kc = 0; kc < 8; ++kc) {
    const int k0 = kc * 16;
    u32 b[4][2];
    #pragma unroll
    for (int ni = 0; ni < 4; ++ni) {
      const __nv_bfloat16* wp = g_Wx1T + (nc0 + 8*ni + g) * 136 + (k0 + 2*c);
      b[ni][0] = __ldg((const u32*)wp);
      b[ni][1] = __ldg((const u32*)(wp + 8));
    }
    #pragma unroll
    for (int mi = 0; mi < 4; ++mi) {
      unsigned aaddr = sbu + SX + (mr0 + 16*mi + rsel) * 272 + (k0 + ksh) * 2;
      u32 a0, a1, a2, a3;
      ldmA(a0, a1, a2, a3, aaddr);
      #pragma unroll
      for (int ni = 0; ni < 4; ++ni)
        mma16816(d[mi][ni], a0, a1, a2, a3, b[ni][0], b[ni][1]);
    }
  }
  // epilogue 3: coef partials
  {
    float cp[4][2];
    #pragma unroll
    for (int mi = 0; mi < 4; ++mi) { cp[mi][0] = 0.f; cp[mi][1] = 0.f; }
    #pragma unroll
    for (int mi = 0; mi < 4; ++mi)
      #pragma unroll
      for (int ni = 0; ni < 4; ++ni) {
        int col = nc0 + 8*ni + 2*c;
        float b0 = sBX1[col], b1 = sBX1[col + 1];
        float w0 = sWX2[col], w1 = sWX2[col + 1];
        float v0 = silu_f(d[mi][ni][0] + b0), v1 = silu_f(d[mi][ni][1] + b1);
        float v2 = silu_f(d[mi][ni][2] + b0), v3 = silu_f(d[mi][ni][3] + b1);
        cp[mi][0] = fmaf(v0, w0, fmaf(v1, w1, cp[mi][0]));
        cp[mi][1] = fmaf(v2, w0, fmaf(v3, w1, cp[mi][1]));
      }
    #pragma unroll
    for (int mi = 0; mi < 4; ++mi)
      #pragma unroll
      for (int rh = 0; rh < 2; ++rh) {
        float p = cp[mi][rh];
        p += __shfl_xor_sync(0xffffffffu, p, 1);
        p += __shfl_xor_sync(0xffffffffu, p, 2);
        if (c == 0) sRedC[(mr0 + 16*mi + 8*rh + g) * 4 + (w & 3)] = p;
      }
  }
  __syncthreads();   // sync6

  if (tid < MT) {
    float sg = sRedG[tid*4+0] + sRedG[tid*4+1] + sRedG[tid*4+2] + sRedG[tid*4+3]
             + *(float*)(sm + SBGV);
    sG[tid] = sigmoid_f(sg);
    float sc = sRedC[tid*4+0] + sRedC[tid*4+1] + sRedC[tid*4+2] + sRedC[tid*4+3];
    sCoef[tid] = tanhf(sc);
  }
  __syncthreads();   // sync7

  // scatter: agg += m2 * g
  {
    const int j = tid & 127, half = tid >> 7;
    #pragma unroll 4
    for (int e = half * 64; e < half * 64 + 64; ++e) {
      if (e0 + e < E) {
        float m2v = __bfloat162float(*(const __nv_bfloat16*)(sm + SX + e * 272 + j * 2));
        atomicAdd(&g_agg[(size_t)sDst[e] * HID + j], m2v * sG[e]);
      }
    }
  }
  if (tid < MT && (e0 + tid < E)) {
    int dd = sDst[tid];
    float cc = sCoef[tid] * sRinv[tid];
    atomicAdd(&g_dx[dd*3+0], sRelX[tid] * cc);
    atomicAdd(&g_dx[dd*3+1], sRelY[tid] * cc);
    atomicAdd(&g_dx[dd*3+2], sRelZ[tid] * cc);
  }
}

// ==================== node kernel: mma.sync version ====================
// smem: tile0 @0 (agg -> nm), tile1 @34816 (h), biases @69632
#define NB1   69632
#define NB2   70144
#define NSMT  70656

__global__ __launch_bounds__(256, 2)
void node_kernel(const float* __restrict__ h,
                 const float* __restrict__ bn1, const float* __restrict__ bn2,
                 float* __restrict__ outH, int N)
{
  extern __shared__ char sm[];
  const unsigned sbu = smem_u32(sm);
  const int tid  = threadIdx.x;
  const int lane = tid & 31;
  const int w    = tid >> 5;
  const int g    = lane >> 2;
  const int c    = lane & 3;
  const int mr0  = (w >> 2) * 64;
  const int nc0  = (w & 3) * 32;
  const int n0   = blockIdx.x * 128;
  const int rsel = lane & 15;
  const int ksh  = (lane >> 4) << 3;

  float* sB1 = (float*)(sm + NB1);
  float* sB2 = (float*)(sm + NB2);
  if (tid < 128) { sB1[tid] = bn1[tid]; sB2[tid] = bn2[tid]; }

  // stage agg -> tile0, h -> tile1 (bf16, stride 272B)
  {
    int j2 = (tid & 63) * 2, half = tid >> 6;
    for (int e = half * 32; e < half * 32 + 32; ++e) {
      int n = min(n0 + e, N - 1);
      float2 va = *(const float2*)(g_agg + (size_t)n * HID + j2);
      float2 vh = __ldg((const float2*)(h + (size_t)n * HID + j2));
      *(u32*)(sm + e * 272 + j2 * 2)         = bf16pack(va.x, va.y);
      *(u32*)(sm + 34816 + e * 272 + j2 * 2) = bf16pack(vh.x, vh.y);
    }
  }
  __syncthreads();

  float d[4][4][4];
  #pragma unroll
  for (int mi = 0; mi < 4; ++mi)
    #pragma unroll
    for (int ni = 0; ni < 4; ++ni) {
      d[mi][ni][0] = 0.f; d[mi][ni][1] = 0.f; d[mi][ni][2] = 0.f; d[mi][ni][3] = 0.f;
    }

  // stage 1: d = agg @ Wn1aT + h @ Wn1bT
  #pragma unroll
  for (int half = 0; half < 2; ++half) {
    const unsigned toff = half ? 34816u : 0u;
    const __nv_bfloat16* W = half ? g_Wn1bT : g_Wn1aT;
    #pragma unroll
    for (int kc = 0; kc < 8; ++kc) {
      const int k0 = kc * 16;
      u32 b[4][2];
      #pragma unroll
      for (int ni = 0; ni < 4; ++ni) {
        const __nv_bfloat16* wp = W + (nc0 + 8*ni + g) * 136 + (k0 + 2*c);
        b[ni][0] = __ldg((const u32*)wp);
        b[ni][1] = __ldg((const u32*)(wp + 8));
      }
      #pragma unroll
      for (int mi = 0; mi < 4; ++mi) {
        unsigned aaddr = sbu + toff + (mr0 + 16*mi + rsel) * 272 + (k0 + ksh) * 2;
        u32 a0, a1, a2, a3;
        ldmA(a0, a1, a2, a3, aaddr);
        #pragma unroll
        for (int ni = 0; ni < 4; ++ni)
          mma16816(d[mi][ni], a0, a1, a2, a3, b[ni][0], b[ni][1]);
      }
    }
  }
  __syncthreads();   // all stage-1 reads done

  // epilogue 1: nm = silu(d + bn1) -> tile0
  #pragma unroll
  for (int mi = 0; mi < 4; ++mi)
    #pragma unroll
    for (int ni = 0; ni < 4; ++ni) {
      int row = mr0 + 16*mi + g, col = nc0 + 8*ni + 2*c;
      float b0 = sB1[col], b1 = sB1[col + 1];
      float v0 = silu_f(d[mi][ni][0] + b0), v1 = silu_f(d[mi][ni][1] + b1);
      float v2 = silu_f(d[mi][ni][2] + b0), v3 = silu_f(d[mi][ni][3] + b1);
      *(u32*)(sm + row * 272 + col * 2)       = bf16pack(v0, v1);
      *(u32*)(sm + (row + 8) * 272 + col * 2) = bf16pack(v2, v3);
    }
  __syncthreads();

  // stage 2: d = nm @ Wn2T
  #pragma unroll
  for (int mi = 0; mi < 4; ++mi)
    #pragma unroll
    for (int ni = 0; ni < 4; ++ni) {
      d[mi][ni][0] = 0.f; d[mi][ni][1] = 0.f; d[mi][ni][2] = 0.f; d[mi][ni][3] = 0.f;
    }
  #pragma unroll
  for (int kc = 0; kc < 8; ++kc) {
    const int k0 = kc * 16;
    u32 b[4][2];
    #pragma unroll
    for (int ni = 0; ni < 4; ++ni) {
      const __nv_bfloat16* wp = g_Wn2T + (nc0 + 8*ni + g) * 136 + (k0 + 2*c);
      b[ni][0] = __ldg((const u32*)wp);
      b[ni][1] = __ldg((const u32*)(wp + 8));
    }
    #pragma unroll
    for (int mi = 0; mi < 4; ++mi) {
      unsigned aaddr = sbu + (mr0 + 16*mi + rsel) * 272 + (k0 + ksh) * 2;
      u32 a0, a1, a2, a3;
      ldmA(a0, a1, a2, a3, aaddr);
      #pragma unroll
      for (int ni = 0; ni < 4; ++ni)
        mma16816(d[mi][ni], a0, a1, a2, a3, b[ni][0], b[ni][1]);
    }
  }

  // epilogue 2: h_out = h(fp32) + d + bn2
  #pragma unroll
  for (int mi = 0; mi < 4; ++mi)
    #pragma unroll
    for (int ni = 0; ni < 4; ++ni) {
      int row0 = mr0 + 16*mi + g, row1 = row0 + 8;
      int col = nc0 + 8*ni + 2*c;
      float b0 = sB2[col], b1 = sB2[col + 1];
      if (n0 + row0 < N) {
        float2 hv = __ldg((const float2*)(h + (size_t)(n0 + row0) * HID + col));
        float2 o; o.x = hv.x + d[mi][ni][0] + b0; o.y = hv.y + d[mi][ni][1] + b1;
        *(float2*)(outH + (size_t)(n0 + row0) * HID + col) = o;
      }
      if (n0 + row1 < N) {
        float2 hv = __ldg((const float2*)(h + (size_t)(n0 + row1) * HID + col));
        float2 o; o.x = hv.x + d[mi][ni][2] + b0; o.y = hv.y + d[mi][ni][3] + b1;
        *(float2*)(outH + (size_t)(n0 + row1) * HID + col) = o;
      }
    }
}

__global__ void xout_kernel(const float* __restrict__ x, const int* __restrict__ mask,
                            float* __restrict__ outX, int N)
{
  int i = blockIdx.x * blockDim.x + threadIdx.x;
  if (i < N * 3) {
    int n = i / 3;
    outX[i] = x[i] + g_dx[i] * (float)mask[n];
  }
}

// ==================== launch ====================
extern "C" void kernel_launch(void* const* d_in, const int* in_sizes, int n_in,
                              void* d_out, int out_size) {
  const float *h, *x, *ea, *We1, *be1, *We2, *be2, *Wg, *bg;
  const float *Wn1, *bn1, *Wn2, *bn2, *Wx1, *bx1, *Wx2;
  const int *ei, *mask;

  const int E = in_sizes[2] / EF;
  const int N = in_sizes[0] / HID;
  const bool setup_order = (in_sizes[3] == 2 * E);

  if (setup_order) {
    h    = (const float*)d_in[0];  x    = (const float*)d_in[1];
    ea   = (const float*)d_in[2];  ei   = (const int*)  d_in[3];
    mask = (const int*)  d_in[4];
    We1  = (const float*)d_in[5];  be1  = (const float*)d_in[6];
    We2  = (const float*)d_in[7];  be2  = (const float*)d_in[8];
    Wg   = (const float*)d_in[9];  bg   = (const float*)d_in[10];
    Wn1  = (const float*)d_in[11]; bn1  = (const float*)d_in[12];
    Wn2  = (const float*)d_in[13]; bn2  = (const float*)d_in[14];
    Wx1  = (const float*)d_in[15]; bx1  = (const float*)d_in[16];
    Wx2  = (const float*)d_in[17];
  } else {
    h    = (const float*)d_in[0];  x    = (const float*)d_in[1];
    ea   = (const float*)d_in[2];
    We1  = (const float*)d_in[3];  be1  = (const float*)d_in[4];
    We2  = (const float*)d_in[5];  be2  = (const float*)d_in[6];
    Wg   = (const float*)d_in[7];  bg   = (const float*)d_in[8];
    Wn1  = (const float*)d_in[9];  bn1  = (const float*)d_in[10];
    Wn2  = (const float*)d_in[11]; bn2  = (const float*)d_in[12];
    Wx1  = (const float*)d_in[13]; bx1  = (const float*)d_in[14];
    Wx2  = (const float*)d_in[15];
    ei   = (const int*)  d_in[16]; mask = (const int*)  d_in[17];
  }

  float* outH = (float*)d_out;
  float* outX = outH + (size_t)N * HID;

  cudaFuncSetAttribute(edge_kernel, cudaFuncAttributeMaxDynamicSharedMemorySize, SMTOT);
  cudaFuncSetAttribute(node_kernel, cudaFuncAttributeMaxDynamicSharedMemorySize, NSMT);

  // launches: zero(1) prep(2) wprep(3) edge(4) node(5) xout(6) -> ncu slot 4 = edge
  zero_kernel<<<(MAXN * HID + 255) / 256, 256>>>();

  prep_kernel<<<(N + TE - 1) / TE, 256>>>(h, We1, N);

  wprep_kernel<<<(128 * 136 + 255) / 256, 256>>>(We1, We2, Wx1, Wn1, Wn2);

  int eblocks = (E + MT - 1) / MT;
  edge_kernel<<<eblocks, 256, SMTOT>>>(x, ea, ei, be1, be2, Wg, bg, bx1, Wx2, E);

  int nblocks = (N + 127) / 128;
  node_kernel<<<nblocks, 256, NSMT>>>(h, bn1, bn2, outH, N);

  xout_kernel<<<(N * 3 + 255) / 256, 256>>>(x, mask, outX, N);
}

// round 16
// speedup vs baseline: 10.6503x; 1.0151x over previous
#include <cuda_runtime.h>
#include <cuda_bf16.h>
#include <math.h>

#define HID   128
#define EF    4
#define NG    20
#define TE    32
#define PITCH 36
#define MAXN  20000
#define CUTOFF 10.0f
#define MT    128        // edges per block (M)

typedef unsigned long long ull;
typedef unsigned u32;

// ==================== device scratch ====================
__device__ float g_agg[MAXN * HID];
__device__ float g_dx [MAXN * 3];
__device__ float g_P  [MAXN * 256];                 // [P_dst | P_src]
// Fragment-packed B weights: [ncblk][kc][lane][8 u32], lane's 8 words contiguous
__device__ __align__(16) u32 g_BW1  [4 * 2 * 32 * 8];   // stage1 (K=32)
__device__ __align__(16) u32 g_BWe2 [4 * 8 * 32 * 8];
__device__ __align__(16) u32 g_BWx1 [4 * 8 * 32 * 8];
__device__ __align__(16) u32 g_BWn1a[4 * 8 * 32 * 8];
__device__ __align__(16) u32 g_BWn1b[4 * 8 * 32 * 8];
__device__ __align__(16) u32 g_BWn2 [4 * 8 * 32 * 8];

// ==================== helpers ====================
__device__ __forceinline__ float silu_f(float v)    { return v / (1.f + __expf(-v)); }
__device__ __forceinline__ float sigmoid_f(float v) { return 1.f / (1.f + __expf(-v)); }
__device__ __forceinline__ u32 bf16pack(float lo, float hi) {
  u32 r;
  asm("cvt.rn.bf16x2.f32 %0, %1, %2;" : "=r"(r) : "f"(hi), "f"(lo));
  return r;
}
__device__ __forceinline__ unsigned smem_u32(const void* p) {
  unsigned a;
  asm("{ .reg .u64 t; cvta.to.shared.u64 t, %1; cvt.u32.u64 %0, t; }" : "=r"(a) : "l"(p));
  return a;
}
__device__ __forceinline__ void mma16816(float d[4], u32 a0, u32 a1, u32 a2, u32 a3,
                                         u32 b0, u32 b1) {
  asm volatile("mma.sync.aligned.m16n8k16.row.col.f32.bf16.bf16.f32 "
    "{%0,%1,%2,%3}, {%4,%5,%6,%7}, {%8,%9}, {%0,%1,%2,%3};"
    : "+f"(d[0]), "+f"(d[1]), "+f"(d[2]), "+f"(d[3])
    : "r"(a0), "r"(a1), "r"(a2), "r"(a3), "r"(b0), "r"(b1));
}
__device__ __forceinline__ void ldmA(u32& a0, u32& a1, u32& a2, u32& a3, unsigned addr) {
  asm volatile("ldmatrix.sync.aligned.m8n8.x4.shared.b16 {%0,%1,%2,%3}, [%4];"
    : "=r"(a0), "=r"(a1), "=r"(a2), "=r"(a3) : "r"(addr));
}

// ==================== edge smem layout (bytes) ====================
#define SDST   0
#define SSRC   512
#define SRELX  1024
#define SRELY  1536
#define SRELZ  2048
#define SRINV  2560
#define SRV    3072
#define SGATE  3584
#define SCOEF  4096
#define SREDG  4608     // 128*4 f32
#define SREDC  6656     // 128*4 f32
#define SBE1   8704
#define SBE2   9216
#define SBX1   9728
#define SWGV   10240
#define SWX2V  10752
#define SBGV   11264
#define SAREST 11392    // 128 x 40 bf16 (stride 80B)   10240
#define SX     21632    // m1 then m2 tile, 128 x 272B  34816
#define SMTOT  56448

// ==================== zero ====================
__global__ void zero_kernel() {
  int i = blockIdx.x * blockDim.x + threadIdx.x;
  if (i < MAXN * HID) g_agg[i] = 0.f;
  if (i < MAXN * 3)   g_dx[i]  = 0.f;
}

// ==================== FFMA2 helpers (prep) ====================
__device__ __forceinline__ ull fma2(ull a, ull b, ull c) {
  ull d; asm("fma.rn.f32x2 %0, %1, %2, %3;" : "=l"(d) : "l"(a), "l"(b), "l"(c)); return d;
}
__device__ __forceinline__ ull pack_dup(float v) {
  ull d; unsigned uu = __float_as_uint(v);
  asm("mov.b64 %0, {%1, %1};" : "=l"(d) : "r"(uu)); return d;
}
__device__ __forceinline__ float2 unpack2(ull v) {
  unsigned lo, hi; asm("mov.b64 {%0, %1}, %2;" : "=r"(lo), "=r"(hi) : "l"(v));
  return make_float2(__uint_as_float(lo), __uint_as_float(hi));
}
template<int K>
__device__ __forceinline__ void gemv32p(const float* __restrict__ W,
                                        const float* __restrict__ sAT,
                                        int j, ull acc[16]) {
  #pragma unroll 4
  for (int k = 0; k < K; ++k) {
    ull w2 = pack_dup(__ldg(W + k * HID + j));
    const ulonglong2* a2 = reinterpret_cast<const ulonglong2*>(sAT + k * PITCH);
    #pragma unroll
    for (int q = 0; q < 8; ++q) {
      ulonglong2 v = a2[q];
      acc[2*q]   = fma2(v.x, w2, acc[2*q]);
      acc[2*q+1] = fma2(v.y, w2, acc[2*q+1]);
    }
  }
}

struct __align__(16) PrepSmem { alignas(16) float sH[HID * PITCH]; };

__global__ __launch_bounds__(256, 3)
void prep_kernel(const float* __restrict__ h, const float* __restrict__ We1, int N)
{
  __shared__ PrepSmem S;
  const int tid = threadIdx.x;
  const int n0  = blockIdx.x * TE;
  for (int idx = tid; idx < HID * TE; idx += 256) {
    int row = idx & 127, e = idx >> 7;
    int n = min(n0 + e, N - 1);
    S.sH[row * PITCH + e] = __ldg(h + (size_t)n * HID + row);
  }
  __syncthreads();
  const int sel = tid >> 7;
  const int j   = tid & 127;
  const float* Wbase = We1 + (size_t)sel * HID * HID;
  ull acc[16];
  #pragma unroll
  for (int q = 0; q < 16; ++q) acc[q] = 0ull;
  gemv32p<HID>(Wbase, S.sH, j, acc);
  #pragma unroll
  for (int q = 0; q < 16; ++q) {
    float2 v = unpack2(acc[q]);
    int eA = 2*q, eB = 2*q+1;
    if (n0 + eA < N) g_P[(size_t)(n0 + eA) * 256 + sel * 128 + j] = v.x;
    if (n0 + eB < N) g_P[(size_t)(n0 + eB) * 256 + sel * 128 + j] = v.y;
  }
}

// Pack weights into per-lane-contiguous fragment order.
// Entry i (< 8192): q=i&7, lane=(i>>3)&31, kc=(i>>8)&7, ncblk=i>>11.
// Fragment word q = ni*2+half maps to W^T[ncblk*32+8*ni+g][kc*16+2*c+8*half .. +1],
// with g=lane>>2, c=lane&3 (same values the kernels previously loaded row-strided).
__global__ void wprep_kernel(const float* __restrict__ We1,
                             const float* __restrict__ We2,
                             const float* __restrict__ Wx1,
                             const float* __restrict__ Wn1,
                             const float* __restrict__ Wn2)
{
  int i = blockIdx.x * blockDim.x + threadIdx.x;
  if (i >= 4 * 8 * 32 * 8) return;
  int q     = i & 7;
  int lane  = (i >> 3) & 31;
  int kc    = (i >> 8) & 7;
  int ncblk = i >> 11;
  int g  = lane >> 2, c = lane & 3;
  int ni = q >> 1,    half = q & 1;
  int row = ncblk * 32 + 8 * ni + g;       // output channel
  int cb  = kc * 16 + 2 * c + 8 * half;    // k column (even)

  g_BWe2 [i] = bf16pack(We2[cb * HID + row],        We2[(cb + 1) * HID + row]);
  g_BWx1 [i] = bf16pack(Wx1[cb * HID + row],        Wx1[(cb + 1) * HID + row]);
  g_BWn1a[i] = bf16pack(Wn1[cb * HID + row],        Wn1[(cb + 1) * HID + row]);
  g_BWn1b[i] = bf16pack(Wn1[(128 + cb) * HID + row], Wn1[(128 + cb + 1) * HID + row]);
  g_BWn2 [i] = bf16pack(Wn2[cb * HID + row],        Wn2[(cb + 1) * HID + row]);

  if (kc < 2) {   // stage-1 (K=32): cols < 24 real, rest zero
    int flat = ((ncblk * 2 + kc) * 32 + lane) * 8 + q;
    float v0 = (cb     < NG + EF) ? We1[(256 + cb)     * HID + row] : 0.f;
    float v1 = (cb + 1 < NG + EF) ? We1[(256 + cb + 1) * HID + row] : 0.f;
    g_BW1[flat] = bf16pack(v0, v1);
  }
}

// Load the 8 fragment words for (ncblk, kc, lane) as 2 coalesced uint4
__device__ __forceinline__ void loadB(const u32* __restrict__ base, int ncblkKC,
                                      int lane, u32 b[4][2]) {
  const uint4* bp = (const uint4*)(base + (ncblkKC * 32 + lane) * 8);
  uint4 B0 = __ldg(bp);
  uint4 B1 = __ldg(bp + 1);
  b[0][0] = B0.x; b[0][1] = B0.y; b[1][0] = B0.z; b[1][1] = B0.w;
  b[2][0] = B1.x; b[2][1] = B1.y; b[3][0] = B1.z; b[3][1] = B1.w;
}

// ==================== edge kernel ====================
__global__ __launch_bounds__(256, 2)
void edge_kernel(const float* __restrict__ x,
                 const float* __restrict__ ea,  const int* __restrict__ ei,
                 const float* __restrict__ be1, const float* __restrict__ be2,
                 const float* __restrict__ Wg,  const float* __restrict__ bg,
                 const float* __restrict__ bx1, const float* __restrict__ Wx2,
                 int E)
{
  extern __shared__ char sm[];
  const unsigned sbu = smem_u32(sm);
  const int tid  = threadIdx.x;
  const int lane = tid & 31;
  const int w    = tid >> 5;
  const int g    = lane >> 2;
  const int c    = lane & 3;
  const int mr0  = (w >> 2) * 64;
  const int nc0  = (w & 3) * 32;
  const int ncb  = (w & 3);            // nc-block index
  const int e0   = blockIdx.x * MT;
  const int rsel = lane & 15;
  const int ksh  = (lane >> 4) << 3;

  int*   sDst  = (int*)(sm + SDST);
  int*   sSrc  = (int*)(sm + SSRC);
  float* sRelX = (float*)(sm + SRELX);
  float* sRelY = (float*)(sm + SRELY);
  float* sRelZ = (float*)(sm + SRELZ);
  float* sRinv = (float*)(sm + SRINV);
  float* sR    = (float*)(sm + SRV);
  float* sG    = (float*)(sm + SGATE);
  float* sCoef = (float*)(sm + SCOEF);
  float* sRedG = (float*)(sm + SREDG);
  float* sRedC = (float*)(sm + SREDC);
  float* sBE1  = (float*)(sm + SBE1);
  float* sBE2  = (float*)(sm + SBE2);
  float* sBX1  = (float*)(sm + SBX1);
  float* sWG   = (float*)(sm + SWGV);
  float* sWX2  = (float*)(sm + SWX2V);

  if (tid < 128) {
    sBE1[tid] = be1[tid]; sBE2[tid] = be2[tid]; sBX1[tid] = bx1[tid];
    sWG[tid]  = Wg[tid];  sWX2[tid] = Wx2[tid];
  }
  if (tid == 0) *(float*)(sm + SBGV) = bg[0];
  if (tid < MT) {
    int eg = min(e0 + tid, E - 1);
    sSrc[tid] = ei[eg];
    sDst[tid] = ei[E + eg];
  }
  __syncthreads();   // sync1

  if (tid < MT) {
    int s = sSrc[tid], d0 = sDst[tid];
    float rx = x[d0*3+0] - x[s*3+0];
    float ry = x[d0*3+1] - x[s*3+1];
    float rz = x[d0*3+2] - x[s*3+2];
    float r  = sqrtf(rx*rx + ry*ry + rz*rz + 1e-8f);
    sRelX[tid] = rx; sRelY[tid] = ry; sRelZ[tid] = rz;
    sR[tid] = r; sRinv[tid] = 1.f / (r + 1.f);
  }

  // stage-1 accumulators pre-loaded with P_dst + P_src
  float d[4][4][4];
  #pragma unroll
  for (int mi = 0; mi < 4; ++mi) {
    int row0 = mr0 + 16*mi + g, row1 = row0 + 8;
    const float* pd0 = g_P + (size_t)sDst[row0] * 256;
    const float* ps0 = g_P + (size_t)sSrc[row0] * 256 + 128;
    const float* pd1 = g_P + (size_t)sDst[row1] * 256;
    const float* ps1 = g_P + (size_t)sSrc[row1] * 256 + 128;
    #pragma unroll
    for (int ni = 0; ni < 4; ++ni) {
      int col = nc0 + 8*ni + 2*c;
      float2 a0 = __ldg((const float2*)(pd0 + col));
      float2 b0 = __ldg((const float2*)(ps0 + col));
      float2 a1 = __ldg((const float2*)(pd1 + col));
      float2 b1 = __ldg((const float2*)(ps1 + col));
      d[mi][ni][0] = a0.x + b0.x; d[mi][ni][1] = a0.y + b0.y;
      d[mi][ni][2] = a1.x + b1.x; d[mi][ni][3] = a1.y + b1.y;
    }
  }
  __syncthreads();   // sync2: sR ready

  // AREST bf16 (stride 80B): cols 0..19 RBF, 20..23 ea, 24..31 zero
  {
    const float step  = CUTOFF / 19.f;
    const float coeff = -0.5f / (step * step);
    for (int i2 = tid; i2 < MT * NG; i2 += 256) {
      int e = i2 & 127, gi = i2 >> 7;
      float diff = sR[e] - (float)gi * step;
      *(__nv_bfloat16*)(sm + SAREST + e * 80 + gi * 2) =
          __float2bfloat16(__expf(coeff * diff * diff));
    }
    for (int i2 = tid; i2 < MT * EF; i2 += 256) {
      int e = i2 & 127, fi = i2 >> 7;
      int eg = min(e0 + e, E - 1);
      *(__nv_bfloat16*)(sm + SAREST + e * 80 + (NG + fi) * 2) =
          __float2bfloat16(ea[(size_t)eg * EF + fi]);
    }
    for (int i2 = tid; i2 < MT * 8; i2 += 256) {
      int e = i2 & 127, k = 24 + (i2 >> 7);
      *(__nv_bfloat16*)(sm + SAREST + e * 80 + k * 2) = __float2bfloat16(0.f);
    }
  }
  __syncthreads();   // sync3

  // ---------------- stage 1: D += rest @ WrestT (K=32) ----------------
  #pragma unroll
  for (int kc = 0; kc < 2; ++kc) {
    const int k0 = kc * 16;
    u32 b[4][2];
    loadB(g_BW1, ncb * 2 + kc, lane, b);
    #pragma unroll
    for (int mi = 0; mi < 4; ++mi) {
      unsigned aaddr = sbu + SAREST + (mr0 + 16*mi + rsel) * 80 + (k0 + ksh) * 2;
      u32 a0, a1, a2, a3;
      ldmA(a0, a1, a2, a3, aaddr);
      #pragma unroll
      for (int ni = 0; ni < 4; ++ni)
        mma16816(d[mi][ni], a0, a1, a2, a3, b[ni][0], b[ni][1]);
    }
  }

  // epilogue 1: m1 = silu(D + be1) -> X
  #pragma unroll
  for (int mi = 0; mi < 4; ++mi)
    #pragma unroll
    for (int ni = 0; ni < 4; ++ni) {
      int row = mr0 + 16*mi + g, col = nc0 + 8*ni + 2*c;
      float b0 = sBE1[col], b1 = sBE1[col + 1];
      float v0 = silu_f(d[mi][ni][0] + b0), v1 = silu_f(d[mi][ni][1] + b1);
      float v2 = silu_f(d[mi][ni][2] + b0), v3 = silu_f(d[mi][ni][3] + b1);
      *(u32*)(sm + SX + row * 272 + col * 2)       = bf16pack(v0, v1);
      *(u32*)(sm + SX + (row + 8) * 272 + col * 2) = bf16pack(v2, v3);
    }
  __syncthreads();   // sync4: X(m1) visible

  // ---------------- stage 2: D = m1 @ We2T ----------------
  #pragma unroll
  for (int mi = 0; mi < 4; ++mi)
    #pragma unroll
    for (int ni = 0; ni < 4; ++ni) {
      d[mi][ni][0] = 0.f; d[mi][ni][1] = 0.f; d[mi][ni][2] = 0.f; d[mi][ni][3] = 0.f;
    }
  #pragma unroll
  for (int kc = 0; kc < 8; ++kc) {
    const int k0 = kc * 16;
    u32 b[4][2];
    loadB(g_BWe2, ncb * 8 + kc, lane, b);
    #pragma unroll
    for (int mi = 0; mi < 4; ++mi) {
      unsigned aaddr = sbu + SX + (mr0 + 16*mi + rsel) * 272 + (k0 + ksh) * 2;
      u32 a0, a1, a2, a3;
      ldmA(a0, a1, a2, a3, aaddr);
      #pragma unroll
      for (int ni = 0; ni < 4; ++ni)
        mma16816(d[mi][ni], a0, a1, a2, a3, b[ni][0], b[ni][1]);
    }
  }
  __syncthreads();   // sync5a: all MMA2 reads of X done

  // epilogue 2: m2 = silu(D + be2) -> X (overwrite m1); gate partials
  {
    float gp[4][2];
    #pragma unroll
    for (int mi = 0; mi < 4; ++mi) { gp[mi][0] = 0.f; gp[mi][1] = 0.f; }
    #pragma unroll
    for (int mi = 0; mi < 4; ++mi)
      #pragma unroll
      for (int ni = 0; ni < 4; ++ni) {
        int row = mr0 + 16*mi + g, col = nc0 + 8*ni + 2*c;
        float b0 = sBE2[col], b1 = sBE2[col + 1];
        float w0 = sWG[col],  w1 = sWG[col + 1];
        float v0 = silu_f(d[mi][ni][0] + b0), v1 = silu_f(d[mi][ni][1] + b1);
        float v2 = silu_f(d[mi][ni][2] + b0), v3 = silu_f(d[mi][ni][3] + b1);
        gp[mi][0] = fmaf(v0, w0, fmaf(v1, w1, gp[mi][0]));
        gp[mi][1] = fmaf(v2, w0, fmaf(v3, w1, gp[mi][1]));
        *(u32*)(sm + SX + row * 272 + col * 2)       = bf16pack(v0, v1);
        *(u32*)(sm + SX + (row + 8) * 272 + col * 2) = bf16pack(v2, v3);
      }
    #pragma unroll
    for (int mi = 0; mi < 4; ++mi)
      #pragma unroll
      for (int rh = 0; rh < 2; ++rh) {
        float p = gp[mi][rh];
        p += __shfl_xor_sync(0xffffffffu, p, 1);
        p += __shfl_xor_sync(0xffffffffu, p, 2);
        if (c == 0) sRedG[(mr0 + 16*mi + 8*rh + g) * 4 + (w & 3)] = p;
      }
  }
  __syncthreads();   // sync5b: X(m2) visible

  // ---------------- stage 3: D = m2 @ Wx1T ----------------
  #pragma unroll
  for (int mi = 0; mi < 4; ++mi)
    #pragma unroll
    for (int ni = 0; ni < 4; ++ni) {
      d[mi][ni][0] = 0.f; d[mi][ni][1] = 0.f; d[mi][ni][2] = 0.f; d[mi][ni][3] = 0.f;
    }
  #pragma unroll
  for (int kc = 0; kc < 8; ++kc) {
    const int k0 = kc * 16;
    u32 b[4][2];
    loadB(g_BWx1, ncb * 8 + kc, lane, b);
    #pragma unroll
    for (int mi = 0; mi < 4; ++mi) {
      unsigned aaddr = sbu + SX + (mr0 + 16*mi + rsel) * 272 + (k0 + ksh) * 2;
      u32 a0, a1, a2, a3;
      ldmA(a0, a1, a2, a3, aaddr);
      #pragma unroll
      for (int ni = 0; ni < 4; ++ni)
        mma16816(d[mi][ni], a0, a1, a2, a3, b[ni][0], b[ni][1]);
    }
  }
  // epilogue 3: coef partials
  {
    float cp[4][2];
    #pragma unroll
    for (int mi = 0; mi < 4; ++mi) { cp[mi][0] = 0.f; cp[mi][1] = 0.f; }
    #pragma unroll
    for (int mi = 0; mi < 4; ++mi)
      #pragma unroll
      for (int ni = 0; ni < 4; ++ni) {
        int col = nc0 + 8*ni + 2*c;
        float b0 = sBX1[col], b1 = sBX1[col + 1];
        float w0 = sWX2[col], w1 = sWX2[col + 1];
        float v0 = silu_f(d[mi][ni][0] + b0), v1 = silu_f(d[mi][ni][1] + b1);
        float v2 = silu_f(d[mi][ni][2] + b0), v3 = silu_f(d[mi][ni][3] + b1);
        cp[mi][0] = fmaf(v0, w0, fmaf(v1, w1, cp[mi][0]));
        cp[mi][1] = fmaf(v2, w0, fmaf(v3, w1, cp[mi][1]));
      }
    #pragma unroll
    for (int mi = 0; mi < 4; ++mi)
      #pragma unroll
      for (int rh = 0; rh < 2; ++rh) {
        float p = cp[mi][rh];
        p += __shfl_xor_sync(0xffffffffu, p, 1);
        p += __shfl_xor_sync(0xffffffffu, p, 2);
        if (c == 0) sRedC[(mr0 + 16*mi + 8*rh + g) * 4 + (w & 3)] = p;
      }
  }
  __syncthreads();   // sync6

  if (tid < MT) {
    float sg = sRedG[tid*4+0] + sRedG[tid*4+1] + sRedG[tid*4+2] + sRedG[tid*4+3]
             + *(float*)(sm + SBGV);
    sG[tid] = sigmoid_f(sg);
    float sc = sRedC[tid*4+0] + sRedC[tid*4+1] + sRedC[tid*4+2] + sRedC[tid*4+3];
    sCoef[tid] = tanhf(sc);
  }
  __syncthreads();   // sync7

  // scatter: agg += m2 * g
  {
    const int j = tid & 127, half = tid >> 7;
    #pragma unroll 4
    for (int e = half * 64; e < half * 64 + 64; ++e) {
      if (e0 + e < E) {
        float m2v = __bfloat162float(*(const __nv_bfloat16*)(sm + SX + e * 272 + j * 2));
        atomicAdd(&g_agg[(size_t)sDst[e] * HID + j], m2v * sG[e]);
      }
    }
  }
  if (tid < MT && (e0 + tid < E)) {
    int dd = sDst[tid];
    float cc = sCoef[tid] * sRinv[tid];
    atomicAdd(&g_dx[dd*3+0], sRelX[tid] * cc);
    atomicAdd(&g_dx[dd*3+1], sRelY[tid] * cc);
    atomicAdd(&g_dx[dd*3+2], sRelZ[tid] * cc);
  }
}

// ==================== node kernel: mma.sync ====================
#define NB1   69632
#define NB2   70144
#define NSMT  70656

__global__ __launch_bounds__(256, 2)
void node_kernel(const float* __restrict__ h,
                 const float* __restrict__ bn1, const float* __restrict__ bn2,
                 float* __restrict__ outH, int N)
{
  extern __shared__ char sm[];
  const unsigned sbu = smem_u32(sm);
  const int tid  = threadIdx.x;
  const int lane = tid & 31;
  const int w    = tid >> 5;
  const int g    = lane >> 2;
  const int c    = lane & 3;
  const int mr0  = (w >> 2) * 64;
  const int nc0  = (w & 3) * 32;
  const int ncb  = (w & 3);
  const int n0   = blockIdx.x * 128;
  const int rsel = lane & 15;
  const int ksh  = (lane >> 4) << 3;

  float* sB1 = (float*)(sm + NB1);
  float* sB2 = (float*)(sm + NB2);
  if (tid < 128) { sB1[tid] = bn1[tid]; sB2[tid] = bn2[tid]; }

  // stage agg -> tile0, h -> tile1 (bf16, stride 272B)
  {
    int j2 = (tid & 63) * 2, half = tid >> 6;
    for (int e = half * 32; e < half * 32 + 32; ++e) {
      int n = min(n0 + e, N - 1);
      float2 va = *(const float2*)(g_agg + (size_t)n * HID + j2);
      float2 vh = __ldg((const float2*)(h + (size_t)n * HID + j2));
      *(u32*)(sm + e * 272 + j2 * 2)         = bf16pack(va.x, va.y);
      *(u32*)(sm + 34816 + e * 272 + j2 * 2) = bf16pack(vh.x, vh.y);
    }
  }
  __syncthreads();

  float d[4][4][4];
  #pragma unroll
  for (int mi = 0; mi < 4; ++mi)
    #pragma unroll
    for (int ni = 0; ni < 4; ++ni) {
      d[mi][ni][0] = 0.f; d[mi][ni][1] = 0.f; d[mi][ni][2] = 0.f; d[mi][ni][3] = 0.f;
    }

  // stage 1: d = agg @ Wn1aT + h @ Wn1bT
  #pragma unroll
  for (int half = 0; half < 2; ++half) {
    const unsigned toff = half ? 34816u : 0u;
    const u32* W = half ? g_BWn1b : g_BWn1a;
    #pragma unroll
    for (int kc = 0; kc < 8; ++kc) {
      const int k0 = kc * 16;
      u32 b[4][2];
      loadB(W, ncb * 8 + kc, lane, b);
      #pragma unroll
      for (int mi = 0; mi < 4; ++mi) {
        unsigned aaddr = sbu + toff + (mr0 + 16*mi + rsel) * 272 + (k0 + ksh) * 2;
        u32 a0, a1, a2, a3;
        ldmA(a0, a1, a2, a3, aaddr);
        #pragma unroll
        for (int ni = 0; ni < 4; ++ni)
          mma16816(d[mi][ni], a0, a1, a2, a3, b[ni][0], b[ni][1]);
      }
    }
  }
  __syncthreads();   // all stage-1 reads done

  // epilogue 1: nm = silu(d + bn1) -> tile0
  #pragma unroll
  for (int mi = 0; mi < 4; ++mi)
    #pragma unroll
    for (int ni = 0; ni < 4; ++ni) {
      int row = mr0 + 16*mi + g, col = nc0 + 8*ni + 2*c;
      float b0 = sB1[col], b1 = sB1[col + 1];
      float v0 = silu_f(d[mi][ni][0] + b0), v1 = silu_f(d[mi][ni][1] + b1);
      float v2 = silu_f(d[mi][ni][2] + b0), v3 = silu_f(d[mi][ni][3] + b1);
      *(u32*)(sm + row * 272 + col * 2)       = bf16pack(v0, v1);
      *(u32*)(sm + (row + 8) * 272 + col * 2) = bf16pack(v2, v3);
    }
  __syncthreads();

  // stage 2: d = nm @ Wn2T
  #pragma unroll
  for (int mi = 0; mi < 4; ++mi)
    #pragma unroll
    for (int ni = 0; ni < 4; ++ni) {
      d[mi][ni][0] = 0.f; d[mi][ni][1] = 0.f; d[mi][ni][2] = 0.f; d[mi][ni][3] = 0.f;
    }
  #pragma unroll
  for (int kc = 0; kc < 8; ++kc) {
    const int k0 = kc * 16;
    u32 b[4][2];
    loadB(g_BWn2, ncb * 8 + kc, lane, b);
    #pragma unroll
    for (int mi = 0; mi < 4; ++mi) {
      unsigned aaddr = sbu + (mr0 + 16*mi + rsel) * 272 + (k0 + ksh) * 2;
      u32 a0, a1, a2, a3;
      ldmA(a0, a1, a2, a3, aaddr);
      #pragma unroll
      for (int ni = 0; ni < 4; ++ni)
        mma16816(d[mi][ni], a0, a1, a2, a3, b[ni][0], b[ni][1]);
    }
  }

  // epilogue 2: h_out = h(fp32) + d + bn2
  #pragma unroll
  for (int mi = 0; mi < 4; ++mi)
    #pragma unroll
    for (int ni = 0; ni < 4; ++ni) {
      int row0 = mr0 + 16*mi + g, row1 = row0 + 8;
      int col = nc0 + 8*ni + 2*c;
      float b0 = sB2[col], b1 = sB2[col + 1];
      if (n0 + row0 < N) {
        float2 hv = __ldg((const float2*)(h + (size_t)(n0 + row0) * HID + col));
        float2 o; o.x = hv.x + d[mi][ni][0] + b0; o.y = hv.y + d[mi][ni][1] + b1;
        *(float2*)(outH + (size_t)(n0 + row0) * HID + col) = o;
      }
      if (n0 + row1 < N) {
        float2 hv = __ldg((const float2*)(h + (size_t)(n0 + row1) * HID + col));
        float2 o; o.x = hv.x + d[mi][ni][2] + b0; o.y = hv.y + d[mi][ni][3] + b1;
        *(float2*)(outH + (size_t)(n0 + row1) * HID + col) = o;
      }
    }
}

__global__ void xout_kernel(const float* __restrict__ x, const int* __restrict__ mask,
                            float* __restrict__ outX, int N)
{
  int i = blockIdx.x * blockDim.x + threadIdx.x;
  if (i < N * 3) {
    int n = i / 3;
    outX[i] = x[i] + g_dx[i] * (float)mask[n];
  }
}

// ==================== launch ====================
extern "C" void kernel_launch(void* const* d_in, const int* in_sizes, int n_in,
                              void* d_out, int out_size) {
  const float *h, *x, *ea, *We1, *be1, *We2, *be2, *Wg, *bg;
  const float *Wn1, *bn1, *Wn2, *bn2, *Wx1, *bx1, *Wx2;
  const int *ei, *mask;

  const int E = in_sizes[2] / EF;
  const int N = in_sizes[0] / HID;
  const bool setup_order = (in_sizes[3] == 2 * E);

  if (setup_order) {
    h    = (const float*)d_in[0];  x    = (const float*)d_in[1];
    ea   = (const float*)d_in[2];  ei   = (const int*)  d_in[3];
    mask = (const int*)  d_in[4];
    We1  = (const float*)d_in[5];  be1  = (const float*)d_in[6];
    We2  = (const float*)d_in[7];  be2  = (const float*)d_in[8];
    Wg   = (const float*)d_in[9];  bg   = (const float*)d_in[10];
    Wn1  = (const float*)d_in[11]; bn1  = (const float*)d_in[12];
    Wn2  = (const float*)d_in[13]; bn2  = (const float*)d_in[14];
    Wx1  = (const float*)d_in[15]; bx1  = (const float*)d_in[16];
    Wx2  = (const float*)d_in[17];
  } else {
    h    = (const float*)d_in[0];  x    = (const float*)d_in[1];
    ea   = (const float*)d_in[2];
    We1  = (const float*)d_in[3];  be1  = (const float*)d_in[4];
    We2  = (const float*)d_in[5];  be2  = (const float*)d_in[6];
    Wg   = (const float*)d_in[7];  bg   = (const float*)d_in[8];
    Wn1  = (const float*)d_in[9];  bn1  = (const float*)d_in[10];
    Wn2  = (const float*)d_in[11]; bn2  = (const float*)d_in[12];
    Wx1  = (const float*)d_in[13]; bx1  = (const float*)d_in[14];
    Wx2  = (const float*)d_in[15];
    ei   = (const int*)  d_in[16]; mask = (const int*)  d_in[17];
  }

  float* outH = (float*)d_out;
  float* outX = outH + (size_t)N * HID;

  cudaFuncSetAttribute(edge_kernel, cudaFuncAttributeMaxDynamicSharedMemorySize, SMTOT);
  cudaFuncSetAttribute(node_kernel, cudaFuncAttributeMaxDynamicSharedMemorySize, NSMT);

  // launches: zero(1) prep(2) wprep(3) edge(4) node(5) xout(6) -> ncu slot 4 = edge
  zero_kernel<<<(MAXN * HID + 255) / 256, 256>>>();

  prep_kernel<<<(N + TE - 1) / TE, 256>>>(h, We1, N);

  wprep_kernel<<<(4 * 8 * 32 * 8 + 255) / 256, 256>>>(We1, We2, Wx1, Wn1, Wn2);

  int eblocks = (E + MT - 1) / MT;
  edge_kernel<<<eblocks, 256, SMTOT>>>(x, ea, ei, be1, be2, Wg, bg, bx1, Wx2, E);

  int nblocks = (N + 127) / 128;
  node_kernel<<<nblocks, 256, NSMT>>>(h, bn1, bn2, outH, N);

  xout_kernel<<<(N * 3 + 255) / 256, 256>>>(x, mask, outX, N);
}